// round 1
// baseline (speedup 1.0000x reference)
#include <cuda_runtime.h>
#include <cstdint>

#define B_   16
#define C_   128
#define HW_  1024
#define NH_  4
#define COND_ 32

// Scratch (device globals; no allocations allowed)
__device__ float g_h [B_*C_*HW_];          // 8 MB   groupnorm output
__device__ float g_q [B_*NH_*C_*HW_];      // 32 MB
__device__ float g_k [B_*NH_*C_*HW_];      // 32 MB
__device__ float g_v [B_*NH_*C_*HW_];      // 32 MB
__device__ float g_hh[B_*6*C_*HW_];        // 48 MB  [16][768][1024]

// ---------------------------------------------------------------------------
// GroupNorm: 32 groups of 4 channels, stats over 4*1024 elements
// ---------------------------------------------------------------------------
__global__ void __launch_bounds__(256) gn_kernel(
    const float* __restrict__ x, const float* __restrict__ scale,
    const float* __restrict__ bias, float* __restrict__ h)
{
    int b = blockIdx.x >> 5, grp = blockIdx.x & 31;
    const float* xp = x + (size_t)(b*C_ + grp*4)*HW_;
    float*       hp = h + (size_t)(b*C_ + grp*4)*HW_;

    float s = 0.f, ss = 0.f;
    for (int i = threadIdx.x; i < 4096; i += 256) {
        float v = xp[i]; s += v; ss += v*v;
    }
    #pragma unroll
    for (int o = 16; o; o >>= 1) {
        s  += __shfl_xor_sync(~0u, s,  o);
        ss += __shfl_xor_sync(~0u, ss, o);
    }
    __shared__ float sh_s[8], sh_ss[8];
    int w = threadIdx.x >> 5;
    if ((threadIdx.x & 31) == 0) { sh_s[w] = s; sh_ss[w] = ss; }
    __syncthreads();
    if (threadIdx.x < 32) {
        s  = (threadIdx.x < 8) ? sh_s [threadIdx.x] : 0.f;
        ss = (threadIdx.x < 8) ? sh_ss[threadIdx.x] : 0.f;
        #pragma unroll
        for (int o = 4; o; o >>= 1) {
            s  += __shfl_xor_sync(~0u, s,  o);
            ss += __shfl_xor_sync(~0u, ss, o);
        }
        if (threadIdx.x == 0) { sh_s[0] = s; sh_ss[0] = ss; }
    }
    __syncthreads();
    float mean = sh_s[0] * (1.f/4096.f);
    float var  = sh_ss[0] * (1.f/4096.f) - mean*mean;
    float inv  = rsqrtf(var + 1e-6f);
    for (int i = threadIdx.x; i < 4096; i += 256) {
        int c = grp*4 + (i >> 10);
        hp[i] = (xp[i] - mean) * inv * scale[c] + bias[c];
    }
}

// ---------------------------------------------------------------------------
// QKV projection: out[o,p] = sum_k X[k,p] * W[k,o] + bias[o]
//   X = concat(h[b] (128), cond[b] (32)),  per batch & projection
// 64x64 tile, BK=16, 256 threads, 4x4 microtile
// ---------------------------------------------------------------------------
__global__ void __launch_bounds__(256) proj_kernel(
    const float* __restrict__ h,  const float* __restrict__ q_cond,
    const float* __restrict__ ka, const float* __restrict__ kb,
    const float* __restrict__ W0, const float* __restrict__ b0,
    const float* __restrict__ W1, const float* __restrict__ b1,
    const float* __restrict__ W2, const float* __restrict__ b2,
    float* __restrict__ qo, float* __restrict__ ko, float* __restrict__ vo)
{
    int pt = blockIdx.x, ot = blockIdx.y;
    int b  = blockIdx.z / 3, pr = blockIdx.z % 3;

    const float* W; const float* bias; float* out; const float* cond;
    if (pr == 0) { W = W0; bias = b0; out = qo; cond = q_cond + (size_t)(b>>1)*COND_*HW_; }
    else {
        cond = (((b & 1) ? kb : ka)) + (size_t)(b>>1)*COND_*HW_;
        if (pr == 1) { W = W1; bias = b1; out = ko; }
        else         { W = W2; bias = b2; out = vo; }
    }
    const float* hb = h + (size_t)b*C_*HW_;
    out += (size_t)b*512*HW_;

    __shared__ float Ws[16][64];
    __shared__ float Xs[16][64];
    float acc[4][4] = {};
    int tx = threadIdx.x & 15, ty = threadIdx.x >> 4;

    for (int k0 = 0; k0 < 160; k0 += 16) {
        #pragma unroll
        for (int r = 0; r < 4; r++) {
            int idx = r*256 + threadIdx.x;
            int kk = idx >> 6, cc = idx & 63;
            Ws[kk][cc] = W[(size_t)(k0+kk)*512 + ot*64 + cc];
            int kin = k0 + kk;
            Xs[kk][cc] = (kin < C_) ? hb[(size_t)kin*HW_ + pt*64 + cc]
                                    : cond[(size_t)(kin-C_)*HW_ + pt*64 + cc];
        }
        __syncthreads();
        #pragma unroll
        for (int kk = 0; kk < 16; kk++) {
            float4 a4 = *(const float4*)&Ws[kk][ty*4];
            float4 x4 = *(const float4*)&Xs[kk][tx*4];
            float a[4] = {a4.x, a4.y, a4.z, a4.w};
            float xr[4] = {x4.x, x4.y, x4.z, x4.w};
            #pragma unroll
            for (int i = 0; i < 4; i++)
                #pragma unroll
                for (int j = 0; j < 4; j++)
                    acc[i][j] += a[i] * xr[j];
        }
        __syncthreads();
    }
    #pragma unroll
    for (int i = 0; i < 4; i++) {
        int row = ot*64 + ty*4 + i;
        float bb = bias[row];
        float4 o4 = make_float4(acc[i][0]+bb, acc[i][1]+bb, acc[i][2]+bb, acc[i][3]+bb);
        *(float4*)&out[(size_t)row*HW_ + pt*64 + tx*4] = o4;
    }
}

// ---------------------------------------------------------------------------
// Attention: flash-style, 64-query tile per block, 16 key tiles of 64
// q,k,v: [C=128][S=1024] channel-major. out: hh slice [128][1024].
// dyn smem: qs [128*64], kvs [max(128*64, 64*129)], ps [64*65]
// ---------------------------------------------------------------------------
#define SM_QS   0
#define SM_KVS  8192
#define SM_PS   (8192 + 8256)
#define SM_FLOATS (8192 + 8256 + 4160)

__global__ void __launch_bounds__(256, 2) attn_kernel(
    const float* __restrict__ gq, const float* __restrict__ gk,
    const float* __restrict__ gv, float* __restrict__ hh)
{
    extern __shared__ float sm[];
    float* qs  = sm + SM_QS;
    float* kvs = sm + SM_KVS;
    float* ps  = sm + SM_PS;

    int qt = blockIdx.x;
    int z  = blockIdx.y;                   // 0..95
    int e  = z & 3, s5 = (z >> 2) % 6, b4 = z / 24;
    const int qtab[6] = {0,1,2,3,0,2};
    const int ktab[6] = {1,0,3,2,2,0};

    const float* q = gq + (size_t)((b4*4 + qtab[s5])*NH_ + e) * (C_*HW_);
    const float* k = gk + (size_t)((b4*4 + ktab[s5])*NH_ + e) * (C_*HW_);
    const float* v = gv + (size_t)((b4*4 + ktab[s5])*NH_ + e) * (C_*HW_);
    int idx0 = s5*512 + e*128;
    float* out = hh + ((size_t)(b4*4 + idx0/768)*768 + (idx0 % 768)) * HW_;

    int tid = threadIdx.x;
    int tx = tid & 15, ty = tid >> 4;

    // load q tile [128][64]
    for (int i = tid; i < C_*64; i += 256) {
        int c = i >> 6, p = i & 63;
        qs[i] = q[(size_t)c*HW_ + qt*64 + p];
    }

    float m[4], l[4], acc[4][8];
    #pragma unroll
    for (int i = 0; i < 4; i++) {
        m[i] = -1e30f; l[i] = 0.f;
        #pragma unroll
        for (int j = 0; j < 8; j++) acc[i][j] = 0.f;
    }
    const float sc = 0.08838834764831845f;  // 1/sqrt(128)

    for (int kt = 0; kt < 16; kt++) {
        __syncthreads();  // kvs free (prev V reads done) / qs loaded
        for (int i = tid; i < C_*64; i += 256) {
            int c = i >> 6, p = i & 63;
            kvs[i] = k[(size_t)c*HW_ + kt*64 + p];
        }
        __syncthreads();

        // scores 4x4 per thread over channel dim
        float sv[4][4] = {};
        #pragma unroll 8
        for (int c = 0; c < C_; c++) {
            float4 q4 = *(const float4*)&qs[c*64 + ty*4];
            float4 k4 = *(const float4*)&kvs[c*64 + tx*4];
            float qa[4] = {q4.x, q4.y, q4.z, q4.w};
            float kb2[4] = {k4.x, k4.y, k4.z, k4.w};
            #pragma unroll
            for (int i = 0; i < 4; i++)
                #pragma unroll
                for (int j = 0; j < 4; j++)
                    sv[i][j] += qa[i] * kb2[j];
        }

        // online softmax per q row
        #pragma unroll
        for (int i = 0; i < 4; i++) {
            #pragma unroll
            for (int j = 0; j < 4; j++) sv[i][j] *= sc;
            float rm = fmaxf(fmaxf(sv[i][0], sv[i][1]), fmaxf(sv[i][2], sv[i][3]));
            #pragma unroll
            for (int o = 1; o < 16; o <<= 1)
                rm = fmaxf(rm, __shfl_xor_sync(~0u, rm, o));
            float mn   = fmaxf(m[i], rm);
            float corr = __expf(m[i] - mn);
            m[i] = mn;
            float rs = 0.f;
            #pragma unroll
            for (int j = 0; j < 4; j++) {
                float p = __expf(sv[i][j] - mn);
                ps[(ty*4 + i)*65 + tx*4 + j] = p;
                rs += p;
            }
            #pragma unroll
            for (int o = 1; o < 16; o <<= 1)
                rs += __shfl_xor_sync(~0u, rs, o);
            l[i] = l[i]*corr + rs;
            #pragma unroll
            for (int j = 0; j < 8; j++) acc[i][j] *= corr;
        }
        __syncthreads();  // scores done reading kvs(k)

        // load v transposed: kvs[p*129 + c]
        for (int i = tid; i < C_*64; i += 256) {
            int c = i >> 6, p = i & 63;
            kvs[p*129 + c] = v[(size_t)c*HW_ + kt*64 + p];
        }
        __syncthreads();

        // PV accumulate: acc[i][j] += p[qrow][kk] * v[kk][tx+16j]
        #pragma unroll 4
        for (int kk = 0; kk < 64; kk++) {
            float pr[4];
            #pragma unroll
            for (int i = 0; i < 4; i++) pr[i] = ps[(ty*4 + i)*65 + kk];
            #pragma unroll
            for (int j = 0; j < 8; j++) {
                float vv = kvs[kk*129 + tx + 16*j];
                #pragma unroll
                for (int i = 0; i < 4; i++) acc[i][j] += pr[i] * vv;
            }
        }
    }

    // epilogue: normalize, transpose through smem, coalesced store
    __syncthreads();
    #pragma unroll
    for (int i = 0; i < 4; i++) {
        float inv = 1.f / l[i];
        #pragma unroll
        for (int j = 0; j < 8; j++)
            qs[(tx + 16*j)*64 + ty*4 + i] = acc[i][j] * inv;
    }
    __syncthreads();
    for (int i = tid; i < C_*64; i += 256) {
        int c = i >> 6, p = i & 63;
        out[(size_t)c*HW_ + qt*64 + p] = qs[i];
    }
}

// ---------------------------------------------------------------------------
// Output projection: out[b,c,p] = x[b,c,p] + sum_u hh[b,u,p]*W3[u,c] + b3[c]
// M=128, N=1024, K=768 per batch
// ---------------------------------------------------------------------------
__global__ void __launch_bounds__(256) out_kernel(
    const float* __restrict__ hh, const float* __restrict__ W3,
    const float* __restrict__ b3, const float* __restrict__ x,
    float* __restrict__ out)
{
    int pt = blockIdx.x;   // 16
    int ot = blockIdx.y;   // 2
    int b  = blockIdx.z;   // 16
    const float* hb = hh + (size_t)b*768*HW_;

    __shared__ float Ws[16][64];
    __shared__ float Xs[16][64];
    float acc[4][4] = {};
    int tx = threadIdx.x & 15, ty = threadIdx.x >> 4;

    for (int k0 = 0; k0 < 768; k0 += 16) {
        #pragma unroll
        for (int r = 0; r < 4; r++) {
            int idx = r*256 + threadIdx.x;
            int kk = idx >> 6, cc = idx & 63;
            Ws[kk][cc] = W3[(size_t)(k0+kk)*128 + ot*64 + cc];
            Xs[kk][cc] = hb[(size_t)(k0+kk)*HW_ + pt*64 + cc];
        }
        __syncthreads();
        #pragma unroll
        for (int kk = 0; kk < 16; kk++) {
            float4 a4 = *(const float4*)&Ws[kk][ty*4];
            float4 x4 = *(const float4*)&Xs[kk][tx*4];
            float a[4] = {a4.x, a4.y, a4.z, a4.w};
            float xr[4] = {x4.x, x4.y, x4.z, x4.w};
            #pragma unroll
            for (int i = 0; i < 4; i++)
                #pragma unroll
                for (int j = 0; j < 4; j++)
                    acc[i][j] += a[i] * xr[j];
        }
        __syncthreads();
    }
    #pragma unroll
    for (int i = 0; i < 4; i++) {
        int row = ot*64 + ty*4 + i;
        float bb = b3[row];
        size_t base = ((size_t)b*C_ + row)*HW_ + pt*64 + tx*4;
        float4 x4 = *(const float4*)&x[base];
        float4 o4 = make_float4(acc[i][0]+bb+x4.x, acc[i][1]+bb+x4.y,
                                acc[i][2]+bb+x4.z, acc[i][3]+bb+x4.w);
        *(float4*)&out[base] = o4;
    }
}

// ---------------------------------------------------------------------------
extern "C" void kernel_launch(void* const* d_in, const int* in_sizes, int n_in,
                              void* d_out, int out_size)
{
    const float* x      = (const float*)d_in[0];
    const float* q_cond = (const float*)d_in[1];
    const float* ka     = (const float*)d_in[2];
    const float* kb     = (const float*)d_in[3];
    const float* gs     = (const float*)d_in[4];
    const float* gb     = (const float*)d_in[5];
    const float* W0 = (const float*)d_in[6];  const float* b0 = (const float*)d_in[7];
    const float* W1 = (const float*)d_in[8];  const float* b1 = (const float*)d_in[9];
    const float* W2 = (const float*)d_in[10]; const float* b2 = (const float*)d_in[11];
    const float* W3 = (const float*)d_in[12]; const float* b3 = (const float*)d_in[13];
    float* out = (float*)d_out;

    float *h, *q, *k, *v, *hh;
    cudaGetSymbolAddress((void**)&h,  g_h);
    cudaGetSymbolAddress((void**)&q,  g_q);
    cudaGetSymbolAddress((void**)&k,  g_k);
    cudaGetSymbolAddress((void**)&v,  g_v);
    cudaGetSymbolAddress((void**)&hh, g_hh);

    static int smem_bytes = SM_FLOATS * (int)sizeof(float);
    cudaFuncSetAttribute(attn_kernel,
                         cudaFuncAttributeMaxDynamicSharedMemorySize, smem_bytes);

    gn_kernel<<<512, 256>>>(x, gs, gb, h);

    dim3 pg(16, 8, 48);
    proj_kernel<<<pg, 256>>>(h, q_cond, ka, kb,
                             W0, b0, W1, b1, W2, b2,
                             q, k, v);

    dim3 ag(16, 96);
    attn_kernel<<<ag, 256, smem_bytes>>>(q, k, v, hh);

    dim3 og(16, 2, 16);
    out_kernel<<<og, 256>>>(hh, W3, b3, x, out);
}

// round 3
// speedup vs baseline: 2.3903x; 2.3903x over previous
#include <cuda_runtime.h>
#include <cstdint>

#define B_   16
#define C_   128
#define HW_  1024
#define NH_  4
#define COND_ 32

// Scratch (device globals; no allocations allowed)
__device__ float g_h [B_*C_*HW_];          // groupnorm output [b][c][s]
__device__ float g_qT[B_*NH_*HW_*C_];      // q transposed [b*4+e][s][c]
__device__ float g_kT[B_*NH_*HW_*C_];      // k transposed [b*4+e][s][c]
__device__ float g_vT[B_*NH_*HW_*C_];      // v transposed [b*4+e][s][c]
__device__ float g_hh[B_*6*C_*HW_];        // [16][768][1024]

// ---------------------------------------------------------------------------
__device__ __forceinline__ uint32_t f2tf(float f) {
    uint32_t u;
    asm("cvt.rna.tf32.f32 %0, %1;" : "=r"(u) : "f"(f));
    return u;
}
__device__ __forceinline__ void mma1688(float c[4], const uint32_t a[4],
                                        uint32_t b0, uint32_t b1) {
    asm volatile("mma.sync.aligned.m16n8k8.row.col.f32.tf32.tf32.f32 "
        "{%0,%1,%2,%3}, {%4,%5,%6,%7}, {%8,%9}, {%0,%1,%2,%3};"
        : "+f"(c[0]), "+f"(c[1]), "+f"(c[2]), "+f"(c[3])
        : "r"(a[0]), "r"(a[1]), "r"(a[2]), "r"(a[3]), "r"(b0), "r"(b1));
}

// ---------------------------------------------------------------------------
// GroupNorm
// ---------------------------------------------------------------------------
__global__ void __launch_bounds__(256) gn_kernel(
    const float* __restrict__ x, const float* __restrict__ scale,
    const float* __restrict__ bias, float* __restrict__ h)
{
    int b = blockIdx.x >> 5, grp = blockIdx.x & 31;
    const float* xp = x + (size_t)(b*C_ + grp*4)*HW_;
    float*       hp = h + (size_t)(b*C_ + grp*4)*HW_;

    float s = 0.f, ss = 0.f;
    for (int i = threadIdx.x; i < 4096; i += 256) {
        float v = xp[i]; s += v; ss += v*v;
    }
    #pragma unroll
    for (int o = 16; o; o >>= 1) {
        s  += __shfl_xor_sync(~0u, s,  o);
        ss += __shfl_xor_sync(~0u, ss, o);
    }
    __shared__ float sh_s[8], sh_ss[8];
    int w = threadIdx.x >> 5;
    if ((threadIdx.x & 31) == 0) { sh_s[w] = s; sh_ss[w] = ss; }
    __syncthreads();
    if (threadIdx.x < 32) {
        s  = (threadIdx.x < 8) ? sh_s [threadIdx.x] : 0.f;
        ss = (threadIdx.x < 8) ? sh_ss[threadIdx.x] : 0.f;
        #pragma unroll
        for (int o = 4; o; o >>= 1) {
            s  += __shfl_xor_sync(~0u, s,  o);
            ss += __shfl_xor_sync(~0u, ss, o);
        }
        if (threadIdx.x == 0) { sh_s[0] = s; sh_ss[0] = ss; }
    }
    __syncthreads();
    float mean = sh_s[0] * (1.f/4096.f);
    float var  = sh_ss[0] * (1.f/4096.f) - mean*mean;
    float inv  = rsqrtf(var + 1e-6f);
    for (int i = threadIdx.x; i < 4096; i += 256) {
        int c = grp*4 + (i >> 10);
        hp[i] = (xp[i] - mean) * inv * scale[c] + bias[c];
    }
}

// ---------------------------------------------------------------------------
// QKV projection. q,k,v all stored transposed [b*4+e][s][c]
// ---------------------------------------------------------------------------
__global__ void __launch_bounds__(256) proj_kernel(
    const float* __restrict__ h,  const float* __restrict__ q_cond,
    const float* __restrict__ ka, const float* __restrict__ kb,
    const float* __restrict__ W0, const float* __restrict__ b0,
    const float* __restrict__ W1, const float* __restrict__ b1,
    const float* __restrict__ W2, const float* __restrict__ b2,
    float* __restrict__ qT, float* __restrict__ kT, float* __restrict__ vT)
{
    int pt = blockIdx.x, ot = blockIdx.y;
    int b  = blockIdx.z / 3, pr = blockIdx.z % 3;

    const float* W; const float* bias; const float* cond;
    if (pr == 0) { W = W0; bias = b0; cond = q_cond + (size_t)(b>>1)*COND_*HW_; }
    else {
        cond = (((b & 1) ? kb : ka)) + (size_t)(b>>1)*COND_*HW_;
        if (pr == 1) { W = W1; bias = b1; }
        else         { W = W2; bias = b2; }
    }
    const float* hb = h + (size_t)b*C_*HW_;

    __shared__ float Ws[16][64];
    __shared__ float Xs[16][64];
    __shared__ float tr[64][65];
    float acc[4][4] = {};
    int tx = threadIdx.x & 15, ty = threadIdx.x >> 4;

    for (int k0 = 0; k0 < 160; k0 += 16) {
        #pragma unroll
        for (int r = 0; r < 4; r++) {
            int idx = r*256 + threadIdx.x;
            int kk = idx >> 6, cc = idx & 63;
            Ws[kk][cc] = W[(size_t)(k0+kk)*512 + ot*64 + cc];
            int kin = k0 + kk;
            Xs[kk][cc] = (kin < C_) ? hb[(size_t)kin*HW_ + pt*64 + cc]
                                    : cond[(size_t)(kin-C_)*HW_ + pt*64 + cc];
        }
        __syncthreads();
        #pragma unroll
        for (int kk = 0; kk < 16; kk++) {
            float4 a4 = *(const float4*)&Ws[kk][ty*4];
            float4 x4 = *(const float4*)&Xs[kk][tx*4];
            float a[4] = {a4.x, a4.y, a4.z, a4.w};
            float xr[4] = {x4.x, x4.y, x4.z, x4.w};
            #pragma unroll
            for (int i = 0; i < 4; i++)
                #pragma unroll
                for (int j = 0; j < 4; j++)
                    acc[i][j] += a[i] * xr[j];
        }
        __syncthreads();
    }

    #pragma unroll
    for (int i = 0; i < 4; i++) {
        float bb = bias[ot*64 + ty*4 + i];
        #pragma unroll
        for (int j = 0; j < 4; j++)
            tr[ty*4 + i][tx*4 + j] = acc[i][j] + bb;
    }
    __syncthreads();
    int e = ot >> 1, c0 = (ot & 1) * 64;
    float* dst = (pr == 0 ? qT : (pr == 1 ? kT : vT)) + (size_t)(b*NH_ + e)*HW_*C_;
    for (int idx = threadIdx.x; idx < 64*16; idx += 256) {
        int sl = idx >> 4, cq = idx & 15;
        float4 v4 = make_float4(tr[cq*4+0][sl], tr[cq*4+1][sl],
                                tr[cq*4+2][sl], tr[cq*4+3][sl]);
        *(float4*)&dst[(size_t)(pt*64 + sl)*C_ + c0 + cq*4] = v4;
    }
}

// ---------------------------------------------------------------------------
// Attention via mma.sync tf32 (m16n8k8).
// Per CTA: 128 queries x 1024 keys, 8 warps, warp w owns q rows [w*16, w*16+16).
// Smem (floats): ksm [64][132] @0, vsm [64][136] @8448, psm [128][68] @17152.
// Q staged through ksm region once; obuf reuses ksm/vsm at epilogue.
// ---------------------------------------------------------------------------
#define PADK 132
#define PADV 136
#define PADP 68
#define VSM_OFF 8448
#define PSM_OFF 17152
#define SMEM_FLOATS (17152 + 128*PADP)

__global__ void __launch_bounds__(256, 1) attn_mma_kernel(
    const float* __restrict__ gqT, const float* __restrict__ gkT,
    const float* __restrict__ gvT, float* __restrict__ hh)
{
    extern __shared__ float sm[];
    uint32_t* smu = (uint32_t*)sm;
    uint32_t* vsm = smu + VSM_OFF;
    uint32_t* psm = smu + PSM_OFF;

    const int tid  = threadIdx.x;
    const int warp = tid >> 5;
    const int lane = tid & 31;
    const int g    = lane >> 2;
    const int t    = lane & 3;
    const int q0   = warp * 16;

    int qt = blockIdx.x;
    int z  = blockIdx.y;
    int e  = z & 3, s5 = (z >> 2) % 6, b4 = z / 24;
    const int qtab[6] = {0,1,2,3,0,2};
    const int ktab[6] = {1,0,3,2,2,0};

    const float* qsrc = gqT + (size_t)((b4*4 + qtab[s5])*NH_ + e)*(HW_*C_) + (size_t)qt*128*C_;
    const float* ksrc = gkT + (size_t)((b4*4 + ktab[s5])*NH_ + e)*(HW_*C_);
    const float* vsrc = gvT + (size_t)((b4*4 + ktab[s5])*NH_ + e)*(HW_*C_);
    int idx0 = s5*512 + e*128;
    float* out = hh + ((size_t)(b4*4 + idx0/768)*768 + (idx0 % 768)) * HW_;

    // ---- stage Q [128][128] (tf32) into smem rows of PADK ----
    #pragma unroll
    for (int it = 0; it < 16; it++) {
        int idx = it*256 + tid;
        int r = idx >> 5, c4 = idx & 31;
        float4 v = *(const float4*)(qsrc + (size_t)r*C_ + c4*4);
        uint4 u = make_uint4(f2tf(v.x), f2tf(v.y), f2tf(v.z), f2tf(v.w));
        *(uint4*)&smu[r*PADK + c4*4] = u;
    }
    __syncthreads();

    // ---- Q fragments: qa[ks][0..3] ----
    uint32_t qa[16][4];
    #pragma unroll
    for (int ks = 0; ks < 16; ks++) {
        int base = (q0 + g)*PADK + ks*8 + t;
        qa[ks][0] = smu[base];
        qa[ks][1] = smu[base + 8*PADK];
        qa[ks][2] = smu[base + 4];
        qa[ks][3] = smu[base + 4 + 8*PADK];
    }
    __syncthreads();

    float o[16][4];
    #pragma unroll
    for (int ct = 0; ct < 16; ct++)
        #pragma unroll
        for (int j = 0; j < 4; j++) o[ct][j] = 0.f;
    float l0 = 0.f, l1 = 0.f;
    const float SC = 0.08838834764831845f;  // 1/sqrt(128)

    for (int kt = 0; kt < 16; kt++) {
        // stage K chunk [64][128] and V chunk [64][128] (tf32)
        #pragma unroll
        for (int it = 0; it < 8; it++) {
            int idx = it*256 + tid;
            int r = idx >> 5, c4 = idx & 31;
            float4 kv = *(const float4*)(ksrc + (size_t)(kt*64 + r)*C_ + c4*4);
            *(uint4*)&smu[r*PADK + c4*4] =
                make_uint4(f2tf(kv.x), f2tf(kv.y), f2tf(kv.z), f2tf(kv.w));
            float4 vv = *(const float4*)(vsrc + (size_t)(kt*64 + r)*C_ + c4*4);
            *(uint4*)&vsm[r*PADV + c4*4] =
                make_uint4(f2tf(vv.x), f2tf(vv.y), f2tf(vv.z), f2tf(vv.w));
        }
        __syncthreads();

        // ---- S = Q K^T, exp, stage P ----
        #pragma unroll
        for (int nt = 0; nt < 8; nt++) {
            float c[4] = {0.f, 0.f, 0.f, 0.f};
            int krow = (nt*8 + g)*PADK + t;
            #pragma unroll
            for (int ks = 0; ks < 16; ks++)
                mma1688(c, qa[ks], smu[krow + ks*8], smu[krow + ks*8 + 4]);

            uint32_t u0 = f2tf(__expf(c[0]*SC));
            uint32_t u1 = f2tf(__expf(c[1]*SC));
            uint32_t u2 = f2tf(__expf(c[2]*SC));
            uint32_t u3 = f2tf(__expf(c[3]*SC));
            l0 += __uint_as_float(u0) + __uint_as_float(u1);
            l1 += __uint_as_float(u2) + __uint_as_float(u3);
            int prow = (q0 + g)*PADP + nt*8 + 2*t;
            *(uint2*)&psm[prow]           = make_uint2(u0, u1);
            *(uint2*)&psm[prow + 8*PADP]  = make_uint2(u2, u3);
        }
        __syncwarp();

        // ---- O += P V ----
        #pragma unroll
        for (int ks = 0; ks < 8; ks++) {
            uint32_t pa[4];
            int pbase = (q0 + g)*PADP + ks*8 + t;
            pa[0] = psm[pbase];
            pa[1] = psm[pbase + 8*PADP];
            pa[2] = psm[pbase + 4];
            pa[3] = psm[pbase + 4 + 8*PADP];
            int vrow0 = (ks*8 + t)*PADV + g;
            int vrow1 = (ks*8 + t + 4)*PADV + g;
            #pragma unroll
            for (int ct = 0; ct < 16; ct++)
                mma1688(o[ct], pa, vsm[vrow0 + ct*8], vsm[vrow1 + ct*8]);
        }
        __syncthreads();
    }

    // ---- row-sum reduce over the 4 lanes of each group ----
    l0 += __shfl_xor_sync(~0u, l0, 1);
    l0 += __shfl_xor_sync(~0u, l0, 2);
    l1 += __shfl_xor_sync(~0u, l1, 1);
    l1 += __shfl_xor_sync(~0u, l1, 2);
    float inv0 = 1.f / l0, inv1 = 1.f / l1;

    // ---- normalize, transpose through smem, coalesced store ----
    #pragma unroll
    for (int ct = 0; ct < 16; ct++) {
        int r0 = (q0 + g)*PADK + ct*8 + 2*t;
        int r1 = (q0 + g + 8)*PADK + ct*8 + 2*t;
        sm[r0]     = o[ct][0]*inv0;
        sm[r0 + 1] = o[ct][1]*inv0;
        sm[r1]     = o[ct][2]*inv1;
        sm[r1 + 1] = o[ct][3]*inv1;
    }
    __syncthreads();
    #pragma unroll
    for (int it = 0; it < 64; it++) {
        int idx = it*256 + tid;
        int c = idx >> 7, q = idx & 127;
        out[(size_t)c*HW_ + qt*128 + q] = sm[q*PADK + c];
    }
}

// ---------------------------------------------------------------------------
// Output projection
// ---------------------------------------------------------------------------
__global__ void __launch_bounds__(256) out_kernel(
    const float* __restrict__ hh, const float* __restrict__ W3,
    const float* __restrict__ b3, const float* __restrict__ x,
    float* __restrict__ out)
{
    int pt = blockIdx.x;
    int ot = blockIdx.y;
    int b  = blockIdx.z;
    const float* hb = hh + (size_t)b*768*HW_;

    __shared__ float Ws[16][64];
    __shared__ float Xs[16][64];
    float acc[4][4] = {};
    int tx = threadIdx.x & 15, ty = threadIdx.x >> 4;

    for (int k0 = 0; k0 < 768; k0 += 16) {
        #pragma unroll
        for (int r = 0; r < 4; r++) {
            int idx = r*256 + threadIdx.x;
            int kk = idx >> 6, cc = idx & 63;
            Ws[kk][cc] = W3[(size_t)(k0+kk)*128 + ot*64 + cc];
            Xs[kk][cc] = hb[(size_t)(k0+kk)*HW_ + pt*64 + cc];
        }
        __syncthreads();
        #pragma unroll
        for (int kk = 0; kk < 16; kk++) {
            float4 a4 = *(const float4*)&Ws[kk][ty*4];
            float4 x4 = *(const float4*)&Xs[kk][tx*4];
            float a[4] = {a4.x, a4.y, a4.z, a4.w};
            float xr[4] = {x4.x, x4.y, x4.z, x4.w};
            #pragma unroll
            for (int i = 0; i < 4; i++)
                #pragma unroll
                for (int j = 0; j < 4; j++)
                    acc[i][j] += a[i] * xr[j];
        }
        __syncthreads();
    }
    #pragma unroll
    for (int i = 0; i < 4; i++) {
        int row = ot*64 + ty*4 + i;
        float bb = b3[row];
        size_t bidx = ((size_t)b*C_ + row)*HW_ + pt*64 + tx*4;
        float4 x4 = *(const float4*)&x[bidx];
        float4 o4 = make_float4(acc[i][0]+bb+x4.x, acc[i][1]+bb+x4.y,
                                acc[i][2]+bb+x4.z, acc[i][3]+bb+x4.w);
        *(float4*)&out[bidx] = o4;
    }
}

// ---------------------------------------------------------------------------
extern "C" void kernel_launch(void* const* d_in, const int* in_sizes, int n_in,
                              void* d_out, int out_size)
{
    const float* x      = (const float*)d_in[0];
    const float* q_cond = (const float*)d_in[1];
    const float* ka     = (const float*)d_in[2];
    const float* kb     = (const float*)d_in[3];
    const float* gs     = (const float*)d_in[4];
    const float* gb     = (const float*)d_in[5];
    const float* W0 = (const float*)d_in[6];  const float* b0 = (const float*)d_in[7];
    const float* W1 = (const float*)d_in[8];  const float* b1 = (const float*)d_in[9];
    const float* W2 = (const float*)d_in[10]; const float* b2 = (const float*)d_in[11];
    const float* W3 = (const float*)d_in[12]; const float* b3 = (const float*)d_in[13];
    float* out = (float*)d_out;

    float *h, *qT, *kT, *vT, *hh;
    cudaGetSymbolAddress((void**)&h,  g_h);
    cudaGetSymbolAddress((void**)&qT, g_qT);
    cudaGetSymbolAddress((void**)&kT, g_kT);
    cudaGetSymbolAddress((void**)&vT, g_vT);
    cudaGetSymbolAddress((void**)&hh, g_hh);

    const int attn_smem = SMEM_FLOATS * (int)sizeof(float);  // ~101 KB
    cudaFuncSetAttribute(attn_mma_kernel,
                         cudaFuncAttributeMaxDynamicSharedMemorySize, attn_smem);

    gn_kernel<<<512, 256>>>(x, gs, gb, h);

    dim3 pg(16, 8, 48);
    proj_kernel<<<pg, 256>>>(h, q_cond, ka, kb,
                             W0, b0, W1, b1, W2, b2,
                             qT, kT, vT);

    dim3 ag(8, 96);
    attn_mma_kernel<<<ag, 256, attn_smem>>>(qT, kT, vT, hh);

    dim3 og(16, 2, 16);
    out_kernel<<<og, 256>>>(hh, W3, b3, x, out);
}

// round 4
// speedup vs baseline: 3.2980x; 1.3797x over previous
#include <cuda_runtime.h>
#include <cstdint>

#define B_   16
#define C_   128
#define HW_  1024
#define NH_  4
#define COND_ 32

// Scratch (device globals; no allocations allowed)
__device__ float g_h [B_*C_*HW_];          // groupnorm output [b][c][s]
__device__ float g_qT[B_*NH_*HW_*C_];      // q transposed [b*4+e][s][c] (tf32 bits)
__device__ float g_kT[B_*NH_*HW_*C_];      // k transposed (tf32 bits)
__device__ float g_vT[B_*NH_*HW_*C_];      // v transposed (tf32 bits)
__device__ float g_hh[B_*6*C_*HW_];        // [16][768][1024]

// ---------------------------------------------------------------------------
__device__ __forceinline__ uint32_t f2tf(float f) {
    uint32_t u;
    asm("cvt.rna.tf32.f32 %0, %1;" : "=r"(u) : "f"(f));
    return u;
}
__device__ __forceinline__ void mma1688(float c[4], const uint32_t a[4],
                                        uint32_t b0, uint32_t b1) {
    asm volatile("mma.sync.aligned.m16n8k8.row.col.f32.tf32.tf32.f32 "
        "{%0,%1,%2,%3}, {%4,%5,%6,%7}, {%8,%9}, {%0,%1,%2,%3};"
        : "+f"(c[0]), "+f"(c[1]), "+f"(c[2]), "+f"(c[3])
        : "r"(a[0]), "r"(a[1]), "r"(a[2]), "r"(a[3]), "r"(b0), "r"(b1));
}

// ---------------------------------------------------------------------------
// GroupNorm
// ---------------------------------------------------------------------------
__global__ void __launch_bounds__(256) gn_kernel(
    const float* __restrict__ x, const float* __restrict__ scale,
    const float* __restrict__ bias, float* __restrict__ h)
{
    int b = blockIdx.x >> 5, grp = blockIdx.x & 31;
    const float* xp = x + (size_t)(b*C_ + grp*4)*HW_;
    float*       hp = h + (size_t)(b*C_ + grp*4)*HW_;

    float s = 0.f, ss = 0.f;
    for (int i = threadIdx.x; i < 4096; i += 256) {
        float v = xp[i]; s += v; ss += v*v;
    }
    #pragma unroll
    for (int o = 16; o; o >>= 1) {
        s  += __shfl_xor_sync(~0u, s,  o);
        ss += __shfl_xor_sync(~0u, ss, o);
    }
    __shared__ float sh_s[8], sh_ss[8];
    int w = threadIdx.x >> 5;
    if ((threadIdx.x & 31) == 0) { sh_s[w] = s; sh_ss[w] = ss; }
    __syncthreads();
    if (threadIdx.x < 32) {
        s  = (threadIdx.x < 8) ? sh_s [threadIdx.x] : 0.f;
        ss = (threadIdx.x < 8) ? sh_ss[threadIdx.x] : 0.f;
        #pragma unroll
        for (int o = 4; o; o >>= 1) {
            s  += __shfl_xor_sync(~0u, s,  o);
            ss += __shfl_xor_sync(~0u, ss, o);
        }
        if (threadIdx.x == 0) { sh_s[0] = s; sh_ss[0] = ss; }
    }
    __syncthreads();
    float mean = sh_s[0] * (1.f/4096.f);
    float var  = sh_ss[0] * (1.f/4096.f) - mean*mean;
    float inv  = rsqrtf(var + 1e-6f);
    for (int i = threadIdx.x; i < 4096; i += 256) {
        int c = grp*4 + (i >> 10);
        hp[i] = (xp[i] - mean) * inv * scale[c] + bias[c];
    }
}

// ---------------------------------------------------------------------------
// QKV projection via tf32 mma. Block: M=128 (head e) x N=128 (s tile), K=160.
// A = W chunk [k][m] natural, B = X chunk [k][n] natural. Pad 136.
// Outputs stored transposed [s][c] with tf32 rounding baked in.
// ---------------------------------------------------------------------------
__global__ void __launch_bounds__(256, 2) proj_mma_kernel(
    const float* __restrict__ h,  const float* __restrict__ q_cond,
    const float* __restrict__ ka, const float* __restrict__ kb,
    const float* __restrict__ W0, const float* __restrict__ b0,
    const float* __restrict__ W1, const float* __restrict__ b1,
    const float* __restrict__ W2, const float* __restrict__ b2,
    float* __restrict__ qT, float* __restrict__ kT, float* __restrict__ vT)
{
    int pt = blockIdx.x;          // n tile (8)
    int e  = blockIdx.y;          // m tile = head (4)
    int b  = blockIdx.z / 3, pr = blockIdx.z % 3;

    const float* W; const float* bias; const float* cond; float* dstb;
    if (pr == 0) { W = W0; bias = b0; dstb = qT; cond = q_cond + (size_t)(b>>1)*COND_*HW_; }
    else {
        cond = (((b & 1) ? kb : ka)) + (size_t)(b>>1)*COND_*HW_;
        if (pr == 1) { W = W1; bias = b1; dstb = kT; }
        else         { W = W2; bias = b2; dstb = vT; }
    }
    const float* hb = h + (size_t)b*C_*HW_;
    float* dst = dstb + (size_t)(b*NH_ + e)*HW_*C_;

    __shared__ uint32_t As[32*136];
    __shared__ uint32_t Bs[32*136];

    const int tid  = threadIdx.x;
    const int warp = tid >> 5;
    const int lane = tid & 31;
    const int g    = lane >> 2;
    const int t    = lane & 3;
    const int q0   = warp * 16;

    float o[16][4];
    #pragma unroll
    for (int ct = 0; ct < 16; ct++)
        #pragma unroll
        for (int j = 0; j < 4; j++) o[ct][j] = 0.f;

    for (int k0 = 0; k0 < 160; k0 += 32) {
        const float* xbase = (k0 < 128) ? (hb + (size_t)k0*HW_)
                                        : (cond + (size_t)(k0 - 128)*HW_);
        #pragma unroll
        for (int it = 0; it < 4; it++) {
            int idx = it*256 + tid;
            int kk = idx >> 5, n4 = idx & 31;
            float4 xv = *(const float4*)(xbase + (size_t)kk*HW_ + pt*128 + n4*4);
            *(uint4*)&Bs[kk*136 + n4*4] =
                make_uint4(f2tf(xv.x), f2tf(xv.y), f2tf(xv.z), f2tf(xv.w));
            float4 wv = *(const float4*)(W + (size_t)(k0 + kk)*512 + e*128 + n4*4);
            *(uint4*)&As[kk*136 + n4*4] =
                make_uint4(f2tf(wv.x), f2tf(wv.y), f2tf(wv.z), f2tf(wv.w));
        }
        __syncthreads();

        uint32_t a[4][4];
        #pragma unroll
        for (int ks = 0; ks < 4; ks++) {
            int r0 = (ks*8 + t)*136, r1 = (ks*8 + t + 4)*136;
            a[ks][0] = As[r0 + q0 + g];
            a[ks][1] = As[r0 + q0 + g + 8];
            a[ks][2] = As[r1 + q0 + g];
            a[ks][3] = As[r1 + q0 + g + 8];
        }
        #pragma unroll
        for (int ct = 0; ct < 16; ct++) {
            #pragma unroll
            for (int ks = 0; ks < 4; ks++) {
                uint32_t bv0 = Bs[(ks*8 + t)*136 + ct*8 + g];
                uint32_t bv1 = Bs[(ks*8 + t + 4)*136 + ct*8 + g];
                mma1688(o[ct], a[ks], bv0, bv1);
            }
        }
        __syncthreads();
    }

    float bb0 = bias[e*128 + q0 + g];
    float bb1 = bias[e*128 + q0 + g + 8];
    #pragma unroll
    for (int ct = 0; ct < 16; ct++) {
        size_t n = (size_t)(pt*128 + ct*8 + 2*t);
        int c0 = q0 + g;
        dst[n*C_ + c0]           = __uint_as_float(f2tf(o[ct][0] + bb0));
        dst[(n + 1)*C_ + c0]     = __uint_as_float(f2tf(o[ct][1] + bb0));
        dst[n*C_ + c0 + 8]       = __uint_as_float(f2tf(o[ct][2] + bb1));
        dst[(n + 1)*C_ + c0 + 8] = __uint_as_float(f2tf(o[ct][3] + bb1));
    }
}

// ---------------------------------------------------------------------------
// Attention via mma.sync tf32 (m16n8k8). Inputs already tf32-rounded.
// ---------------------------------------------------------------------------
#define PADK 132
#define PADV 136
#define PADP 68
#define VSM_OFF 8448
#define PSM_OFF 17152
#define SMEM_FLOATS (17152 + 128*PADP)

__global__ void __launch_bounds__(256, 1) attn_mma_kernel(
    const float* __restrict__ gqT, const float* __restrict__ gkT,
    const float* __restrict__ gvT, float* __restrict__ hh)
{
    extern __shared__ float sm[];
    uint32_t* smu = (uint32_t*)sm;
    uint32_t* vsm = smu + VSM_OFF;
    uint32_t* psm = smu + PSM_OFF;

    const int tid  = threadIdx.x;
    const int warp = tid >> 5;
    const int lane = tid & 31;
    const int g    = lane >> 2;
    const int t    = lane & 3;
    const int q0   = warp * 16;

    int qt = blockIdx.x;
    int z  = blockIdx.y;
    int e  = z & 3, s5 = (z >> 2) % 6, b4 = z / 24;
    const int qtab[6] = {0,1,2,3,0,2};
    const int ktab[6] = {1,0,3,2,2,0};

    const float* qsrc = gqT + (size_t)((b4*4 + qtab[s5])*NH_ + e)*(HW_*C_) + (size_t)qt*128*C_;
    const float* ksrc = gkT + (size_t)((b4*4 + ktab[s5])*NH_ + e)*(HW_*C_);
    const float* vsrc = gvT + (size_t)((b4*4 + ktab[s5])*NH_ + e)*(HW_*C_);
    int idx0 = s5*512 + e*128;
    float* out = hh + ((size_t)(b4*4 + idx0/768)*768 + (idx0 % 768)) * HW_;

    // ---- stage Q [128][128] (already tf32) ----
    #pragma unroll
    for (int it = 0; it < 16; it++) {
        int idx = it*256 + tid;
        int r = idx >> 5, c4 = idx & 31;
        *(float4*)&sm[r*PADK + c4*4] = *(const float4*)(qsrc + (size_t)r*C_ + c4*4);
    }
    __syncthreads();

    uint32_t qa[16][4];
    #pragma unroll
    for (int ks = 0; ks < 16; ks++) {
        int base = (q0 + g)*PADK + ks*8 + t;
        qa[ks][0] = smu[base];
        qa[ks][1] = smu[base + 8*PADK];
        qa[ks][2] = smu[base + 4];
        qa[ks][3] = smu[base + 4 + 8*PADK];
    }
    __syncthreads();

    float o[16][4];
    #pragma unroll
    for (int ct = 0; ct < 16; ct++)
        #pragma unroll
        for (int j = 0; j < 4; j++) o[ct][j] = 0.f;
    float l0 = 0.f, l1 = 0.f;
    const float SC = 0.08838834764831845f;  // 1/sqrt(128)

    for (int kt = 0; kt < 16; kt++) {
        #pragma unroll
        for (int it = 0; it < 8; it++) {
            int idx = it*256 + tid;
            int r = idx >> 5, c4 = idx & 31;
            *(float4*)&sm[r*PADK + c4*4] =
                *(const float4*)(ksrc + (size_t)(kt*64 + r)*C_ + c4*4);
            *(float4*)&((float*)vsm)[r*PADV + c4*4] =
                *(const float4*)(vsrc + (size_t)(kt*64 + r)*C_ + c4*4);
        }
        __syncthreads();

        #pragma unroll
        for (int nt = 0; nt < 8; nt++) {
            float c[4] = {0.f, 0.f, 0.f, 0.f};
            int krow = (nt*8 + g)*PADK + t;
            #pragma unroll
            for (int ks = 0; ks < 16; ks++)
                mma1688(c, qa[ks], smu[krow + ks*8], smu[krow + ks*8 + 4]);

            uint32_t u0 = f2tf(__expf(c[0]*SC));
            uint32_t u1 = f2tf(__expf(c[1]*SC));
            uint32_t u2 = f2tf(__expf(c[2]*SC));
            uint32_t u3 = f2tf(__expf(c[3]*SC));
            l0 += __uint_as_float(u0) + __uint_as_float(u1);
            l1 += __uint_as_float(u2) + __uint_as_float(u3);
            int prow = (q0 + g)*PADP + nt*8 + 2*t;
            *(uint2*)&psm[prow]          = make_uint2(u0, u1);
            *(uint2*)&psm[prow + 8*PADP] = make_uint2(u2, u3);
        }
        __syncwarp();

        #pragma unroll
        for (int ks = 0; ks < 8; ks++) {
            uint32_t pa[4];
            int pbase = (q0 + g)*PADP + ks*8 + t;
            pa[0] = psm[pbase];
            pa[1] = psm[pbase + 8*PADP];
            pa[2] = psm[pbase + 4];
            pa[3] = psm[pbase + 4 + 8*PADP];
            int vrow0 = (ks*8 + t)*PADV + g;
            int vrow1 = (ks*8 + t + 4)*PADV + g;
            #pragma unroll
            for (int ct = 0; ct < 16; ct++)
                mma1688(o[ct], pa, vsm[vrow0 + ct*8], vsm[vrow1 + ct*8]);
        }
        __syncthreads();
    }

    l0 += __shfl_xor_sync(~0u, l0, 1);
    l0 += __shfl_xor_sync(~0u, l0, 2);
    l1 += __shfl_xor_sync(~0u, l1, 1);
    l1 += __shfl_xor_sync(~0u, l1, 2);
    float inv0 = 1.f / l0, inv1 = 1.f / l1;

    #pragma unroll
    for (int ct = 0; ct < 16; ct++) {
        int r0 = (q0 + g)*PADK + ct*8 + 2*t;
        int r1 = (q0 + g + 8)*PADK + ct*8 + 2*t;
        sm[r0]     = o[ct][0]*inv0;
        sm[r0 + 1] = o[ct][1]*inv0;
        sm[r1]     = o[ct][2]*inv1;
        sm[r1 + 1] = o[ct][3]*inv1;
    }
    __syncthreads();
    #pragma unroll
    for (int it = 0; it < 64; it++) {
        int idx = it*256 + tid;
        int c = idx >> 7, q = idx & 127;
        out[(size_t)c*HW_ + qt*128 + q] = sm[q*PADK + c];
    }
}

// ---------------------------------------------------------------------------
// Output projection via tf32 mma. Block: M=128 (all c) x N=128 (p tile),
// K=768 in 12 chunks of 64. Fused bias + skip.
// ---------------------------------------------------------------------------
__global__ void __launch_bounds__(256, 1) out_mma_kernel(
    const float* __restrict__ hh, const float* __restrict__ W3,
    const float* __restrict__ b3, const float* __restrict__ x,
    float* __restrict__ out)
{
    extern __shared__ uint32_t osm[];
    uint32_t* As = osm;              // [64][136]
    uint32_t* Bs = osm + 64*136;     // [64][136]

    int pt = blockIdx.x;   // 8
    int b  = blockIdx.y;   // 16
    const float* hb = hh + (size_t)b*768*HW_;

    const int tid  = threadIdx.x;
    const int warp = tid >> 5;
    const int lane = tid & 31;
    const int g    = lane >> 2;
    const int t    = lane & 3;
    const int q0   = warp * 16;

    float o[16][4];
    #pragma unroll
    for (int ct = 0; ct < 16; ct++)
        #pragma unroll
        for (int j = 0; j < 4; j++) o[ct][j] = 0.f;

    for (int k0 = 0; k0 < 768; k0 += 64) {
        #pragma unroll
        for (int it = 0; it < 8; it++) {
            int idx = it*256 + tid;
            int kk = idx >> 5, n4 = idx & 31;
            float4 hv = *(const float4*)(hb + (size_t)(k0 + kk)*HW_ + pt*128 + n4*4);
            *(uint4*)&Bs[kk*136 + n4*4] =
                make_uint4(f2tf(hv.x), f2tf(hv.y), f2tf(hv.z), f2tf(hv.w));
            float4 wv = *(const float4*)(W3 + (size_t)(k0 + kk)*128 + n4*4);
            *(uint4*)&As[kk*136 + n4*4] =
                make_uint4(f2tf(wv.x), f2tf(wv.y), f2tf(wv.z), f2tf(wv.w));
        }
        __syncthreads();

        #pragma unroll
        for (int ks = 0; ks < 8; ks++) {
            uint32_t a[4];
            int r0 = (ks*8 + t)*136, r1 = (ks*8 + t + 4)*136;
            a[0] = As[r0 + q0 + g];
            a[1] = As[r0 + q0 + g + 8];
            a[2] = As[r1 + q0 + g];
            a[3] = As[r1 + q0 + g + 8];
            #pragma unroll
            for (int ct = 0; ct < 16; ct++) {
                uint32_t bv0 = Bs[(ks*8 + t)*136 + ct*8 + g];
                uint32_t bv1 = Bs[(ks*8 + t + 4)*136 + ct*8 + g];
                mma1688(o[ct], a, bv0, bv1);
            }
        }
        __syncthreads();
    }

    float bb0 = b3[q0 + g];
    float bb1 = b3[q0 + g + 8];
    #pragma unroll
    for (int ct = 0; ct < 16; ct++) {
        size_t a0 = ((size_t)b*C_ + q0 + g)*HW_ + pt*128 + ct*8 + 2*t;
        size_t a1 = ((size_t)b*C_ + q0 + g + 8)*HW_ + pt*128 + ct*8 + 2*t;
        float2 x0 = *(const float2*)&x[a0];
        float2 x1 = *(const float2*)&x[a1];
        *(float2*)&out[a0] = make_float2(o[ct][0] + bb0 + x0.x, o[ct][1] + bb0 + x0.y);
        *(float2*)&out[a1] = make_float2(o[ct][2] + bb1 + x1.x, o[ct][3] + bb1 + x1.y);
    }
}

// ---------------------------------------------------------------------------
extern "C" void kernel_launch(void* const* d_in, const int* in_sizes, int n_in,
                              void* d_out, int out_size)
{
    const float* x      = (const float*)d_in[0];
    const float* q_cond = (const float*)d_in[1];
    const float* ka     = (const float*)d_in[2];
    const float* kb     = (const float*)d_in[3];
    const float* gs     = (const float*)d_in[4];
    const float* gb     = (const float*)d_in[5];
    const float* W0 = (const float*)d_in[6];  const float* b0 = (const float*)d_in[7];
    const float* W1 = (const float*)d_in[8];  const float* b1 = (const float*)d_in[9];
    const float* W2 = (const float*)d_in[10]; const float* b2 = (const float*)d_in[11];
    const float* W3 = (const float*)d_in[12]; const float* b3 = (const float*)d_in[13];
    float* out = (float*)d_out;

    float *h, *qT, *kT, *vT, *hh;
    cudaGetSymbolAddress((void**)&h,  g_h);
    cudaGetSymbolAddress((void**)&qT, g_qT);
    cudaGetSymbolAddress((void**)&kT, g_kT);
    cudaGetSymbolAddress((void**)&vT, g_vT);
    cudaGetSymbolAddress((void**)&hh, g_hh);

    const int attn_smem = SMEM_FLOATS * (int)sizeof(float);  // ~103 KB
    cudaFuncSetAttribute(attn_mma_kernel,
                         cudaFuncAttributeMaxDynamicSharedMemorySize, attn_smem);
    const int out_smem = 2 * 64 * 136 * (int)sizeof(uint32_t);  // ~70 KB
    cudaFuncSetAttribute(out_mma_kernel,
                         cudaFuncAttributeMaxDynamicSharedMemorySize, out_smem);

    gn_kernel<<<512, 256>>>(x, gs, gb, h);

    dim3 pg(8, 4, 48);
    proj_mma_kernel<<<pg, 256>>>(h, q_cond, ka, kb,
                                 W0, b0, W1, b1, W2, b2,
                                 qT, kT, vT);

    dim3 ag(8, 96);
    attn_mma_kernel<<<ag, 256, attn_smem>>>(qT, kT, vT, hh);

    dim3 og(8, 16);
    out_mma_kernel<<<og, 256, out_smem>>>(hh, W3, b3, x, out);
}

// round 5
// speedup vs baseline: 6.0956x; 1.8483x over previous
#include <cuda_runtime.h>
#include <cuda_bf16.h>
#include <cstdint>

#define B_   16
#define C_   128
#define HW_  1024
#define NH_  4
#define COND_ 32

// Scratch (device globals; no allocations allowed)
__device__ float          g_h  [B_*C_*HW_];        // groupnorm output [b][c][s]
__device__ __nv_bfloat16  g_q16[B_*NH_*HW_*C_];    // q [b*4+e][s][c] bf16
__device__ __nv_bfloat16  g_k16[B_*NH_*HW_*C_];    // k bf16
__device__ __nv_bfloat16  g_v16[B_*NH_*HW_*C_];    // v bf16
__device__ float          g_hh [B_*6*C_*HW_];      // [16][768][1024]

// ---------------------------------------------------------------------------
__device__ __forceinline__ uint32_t smem_u32(const void* p) {
    uint32_t a;
    asm("{ .reg .u64 t; cvta.to.shared.u64 t, %1; cvt.u32.u64 %0, t; }"
        : "=r"(a) : "l"(p));
    return a;
}
__device__ __forceinline__ uint32_t f2tf(float f) {
    uint32_t u;
    asm("cvt.rna.tf32.f32 %0, %1;" : "=r"(u) : "f"(f));
    return u;
}
__device__ __forceinline__ uint32_t pack_bf16(float lo, float hi) {
    uint32_t r;
    asm("cvt.rn.bf16x2.f32 %0, %1, %2;" : "=r"(r) : "f"(hi), "f"(lo));
    return r;
}
__device__ __forceinline__ float fast_ex2(float x) {
    float y;
    asm("ex2.approx.f32 %0, %1;" : "=f"(y) : "f"(x));
    return y;
}
__device__ __forceinline__ void mma1688(float c[4], const uint32_t a[4],
                                        uint32_t b0, uint32_t b1) {
    asm volatile("mma.sync.aligned.m16n8k8.row.col.f32.tf32.tf32.f32 "
        "{%0,%1,%2,%3}, {%4,%5,%6,%7}, {%8,%9}, {%0,%1,%2,%3};"
        : "+f"(c[0]), "+f"(c[1]), "+f"(c[2]), "+f"(c[3])
        : "r"(a[0]), "r"(a[1]), "r"(a[2]), "r"(a[3]), "r"(b0), "r"(b1));
}
__device__ __forceinline__ void mma_bf16(float c[4], const uint32_t a[4],
                                         uint32_t b0, uint32_t b1) {
    asm volatile("mma.sync.aligned.m16n8k16.row.col.f32.bf16.bf16.f32 "
        "{%0,%1,%2,%3}, {%4,%5,%6,%7}, {%8,%9}, {%0,%1,%2,%3};"
        : "+f"(c[0]), "+f"(c[1]), "+f"(c[2]), "+f"(c[3])
        : "r"(a[0]), "r"(a[1]), "r"(a[2]), "r"(a[3]), "r"(b0), "r"(b1));
}
__device__ __forceinline__ void ldsm_x4(uint32_t r[4], uint32_t addr) {
    asm volatile("ldmatrix.sync.aligned.m8n8.x4.shared.b16 {%0,%1,%2,%3}, [%4];"
        : "=r"(r[0]), "=r"(r[1]), "=r"(r[2]), "=r"(r[3]) : "r"(addr));
}
__device__ __forceinline__ void ldsm_x4t(uint32_t r[4], uint32_t addr) {
    asm volatile("ldmatrix.sync.aligned.m8n8.x4.trans.shared.b16 {%0,%1,%2,%3}, [%4];"
        : "=r"(r[0]), "=r"(r[1]), "=r"(r[2]), "=r"(r[3]) : "r"(addr));
}

// ---------------------------------------------------------------------------
// GroupNorm
// ---------------------------------------------------------------------------
__global__ void __launch_bounds__(256) gn_kernel(
    const float* __restrict__ x, const float* __restrict__ scale,
    const float* __restrict__ bias, float* __restrict__ h)
{
    int b = blockIdx.x >> 5, grp = blockIdx.x & 31;
    const float* xp = x + (size_t)(b*C_ + grp*4)*HW_;
    float*       hp = h + (size_t)(b*C_ + grp*4)*HW_;

    float s = 0.f, ss = 0.f;
    for (int i = threadIdx.x; i < 4096; i += 256) {
        float v = xp[i]; s += v; ss += v*v;
    }
    #pragma unroll
    for (int o = 16; o; o >>= 1) {
        s  += __shfl_xor_sync(~0u, s,  o);
        ss += __shfl_xor_sync(~0u, ss, o);
    }
    __shared__ float sh_s[8], sh_ss[8];
    int w = threadIdx.x >> 5;
    if ((threadIdx.x & 31) == 0) { sh_s[w] = s; sh_ss[w] = ss; }
    __syncthreads();
    if (threadIdx.x < 32) {
        s  = (threadIdx.x < 8) ? sh_s [threadIdx.x] : 0.f;
        ss = (threadIdx.x < 8) ? sh_ss[threadIdx.x] : 0.f;
        #pragma unroll
        for (int o = 4; o; o >>= 1) {
            s  += __shfl_xor_sync(~0u, s,  o);
            ss += __shfl_xor_sync(~0u, ss, o);
        }
        if (threadIdx.x == 0) { sh_s[0] = s; sh_ss[0] = ss; }
    }
    __syncthreads();
    float mean = sh_s[0] * (1.f/4096.f);
    float var  = sh_ss[0] * (1.f/4096.f) - mean*mean;
    float inv  = rsqrtf(var + 1e-6f);
    for (int i = threadIdx.x; i < 4096; i += 256) {
        int c = grp*4 + (i >> 10);
        hp[i] = (xp[i] - mean) * inv * scale[c] + bias[c];
    }
}

// ---------------------------------------------------------------------------
// QKV projection via tf32 mma, M = spatial (128), N = channels (head, 128),
// K = 160. A = X^T from Xs[k][s], B = W from Ws[k][cout].
// Output: bf16 [b*4+e][s][c] with packed bf16x2 stores.
// ---------------------------------------------------------------------------
__global__ void __launch_bounds__(256, 2) proj_mma_kernel(
    const float* __restrict__ h,  const float* __restrict__ q_cond,
    const float* __restrict__ ka, const float* __restrict__ kb,
    const float* __restrict__ W0, const float* __restrict__ b0,
    const float* __restrict__ W1, const float* __restrict__ b1,
    const float* __restrict__ W2, const float* __restrict__ b2,
    __nv_bfloat16* __restrict__ q16, __nv_bfloat16* __restrict__ k16,
    __nv_bfloat16* __restrict__ v16)
{
    int pt = blockIdx.x;          // spatial tile (8)
    int e  = blockIdx.y;          // head (4)
    int b  = blockIdx.z / 3, pr = blockIdx.z % 3;

    const float* W; const float* bias; const float* cond; __nv_bfloat16* dstb;
    if (pr == 0) { W = W0; bias = b0; dstb = q16; cond = q_cond + (size_t)(b>>1)*COND_*HW_; }
    else {
        cond = (((b & 1) ? kb : ka)) + (size_t)(b>>1)*COND_*HW_;
        if (pr == 1) { W = W1; bias = b1; dstb = k16; }
        else         { W = W2; bias = b2; dstb = v16; }
    }
    const float* hb = h + (size_t)b*C_*HW_;
    __nv_bfloat16* dst = dstb + (size_t)(b*NH_ + e)*HW_*C_;

    __shared__ uint32_t Xs[32*136];
    __shared__ uint32_t Ws[32*136];

    const int tid  = threadIdx.x;
    const int warp = tid >> 5;
    const int lane = tid & 31;
    const int g    = lane >> 2;
    const int t    = lane & 3;
    const int q0   = warp * 16;   // spatial rows within tile

    float o[16][4];
    #pragma unroll
    for (int ct = 0; ct < 16; ct++)
        #pragma unroll
        for (int j = 0; j < 4; j++) o[ct][j] = 0.f;

    for (int k0 = 0; k0 < 160; k0 += 32) {
        const float* xbase = (k0 < 128) ? (hb + (size_t)k0*HW_)
                                        : (cond + (size_t)(k0 - 128)*HW_);
        #pragma unroll
        for (int it = 0; it < 4; it++) {
            int idx = it*256 + tid;
            int kk = idx >> 5, n4 = idx & 31;
            float4 xv = *(const float4*)(xbase + (size_t)kk*HW_ + pt*128 + n4*4);
            *(uint4*)&Xs[kk*136 + n4*4] =
                make_uint4(f2tf(xv.x), f2tf(xv.y), f2tf(xv.z), f2tf(xv.w));
            float4 wv = *(const float4*)(W + (size_t)(k0 + kk)*512 + e*128 + n4*4);
            *(uint4*)&Ws[kk*136 + n4*4] =
                make_uint4(f2tf(wv.x), f2tf(wv.y), f2tf(wv.z), f2tf(wv.w));
        }
        __syncthreads();

        uint32_t a[4][4];
        #pragma unroll
        for (int ks = 0; ks < 4; ks++) {
            int r0 = (ks*8 + t)*136, r1 = (ks*8 + t + 4)*136;
            a[ks][0] = Xs[r0 + q0 + g];
            a[ks][1] = Xs[r0 + q0 + g + 8];
            a[ks][2] = Xs[r1 + q0 + g];
            a[ks][3] = Xs[r1 + q0 + g + 8];
        }
        #pragma unroll
        for (int ct = 0; ct < 16; ct++) {
            #pragma unroll
            for (int ks = 0; ks < 4; ks++) {
                uint32_t bv0 = Ws[(ks*8 + t)*136 + ct*8 + g];
                uint32_t bv1 = Ws[(ks*8 + t + 4)*136 + ct*8 + g];
                mma1688(o[ct], a[ks], bv0, bv1);
            }
        }
        __syncthreads();
    }

    int s_row = pt*128 + q0 + g;
    #pragma unroll
    for (int ct = 0; ct < 16; ct++) {
        int c = ct*8 + 2*t;
        float bL = bias[e*128 + c], bH = bias[e*128 + c + 1];
        uint32_t p0 = pack_bf16(o[ct][0] + bL, o[ct][1] + bH);
        uint32_t p1 = pack_bf16(o[ct][2] + bL, o[ct][3] + bH);
        *(uint32_t*)&dst[(size_t)s_row*C_ + c]       = p0;
        *(uint32_t*)&dst[(size_t)(s_row + 8)*C_ + c] = p1;
    }
}

// ---------------------------------------------------------------------------
// Attention via bf16 mma.sync (m16n8k16) + ldmatrix. P stays in registers.
// Per CTA: 128 queries x 1024 keys (16 chunks of 64).
// smem: ksm [64][136]b16 @0, vsm @17408; Q stage aliases both; epilogue
// fp32 [128][132] aliases all. Total 67584 B.
// ---------------------------------------------------------------------------
#define PAD16 136
#define VOFF_B 17408
#define ATTN_SMEM 67584

__global__ void __launch_bounds__(256, 2) attn_bf16_kernel(
    const __nv_bfloat16* __restrict__ gq, const __nv_bfloat16* __restrict__ gk,
    const __nv_bfloat16* __restrict__ gv, float* __restrict__ hh)
{
    extern __shared__ char smraw[];
    __nv_bfloat16* qsm = (__nv_bfloat16*)smraw;            // [128][136]
    __nv_bfloat16* ksm = (__nv_bfloat16*)smraw;            // [64][136]
    __nv_bfloat16* vsm = (__nv_bfloat16*)(smraw + VOFF_B); // [64][136]
    float*         osm = (float*)smraw;                    // [128][132]
    const uint32_t smbase = smem_u32(smraw);

    const int tid  = threadIdx.x;
    const int warp = tid >> 5;
    const int lane = tid & 31;
    const int g    = lane >> 2;
    const int t    = lane & 3;
    const int q0   = warp * 16;

    int qt = blockIdx.x;
    int z  = blockIdx.y;
    int e  = z & 3, s5 = (z >> 2) % 6, b4 = z / 24;
    const int qtab[6] = {0,1,2,3,0,2};
    const int ktab[6] = {1,0,3,2,2,0};

    const __nv_bfloat16* qsrc = gq + (size_t)((b4*4 + qtab[s5])*NH_ + e)*(HW_*C_)
                                   + (size_t)qt*128*C_;
    const __nv_bfloat16* ksrc = gk + (size_t)((b4*4 + ktab[s5])*NH_ + e)*(HW_*C_);
    const __nv_bfloat16* vsrc = gv + (size_t)((b4*4 + ktab[s5])*NH_ + e)*(HW_*C_);
    int idx0 = s5*512 + e*128;
    float* out = hh + ((size_t)(b4*4 + idx0/768)*768 + (idx0 % 768)) * HW_;

    // ---- stage Q [128][136] bf16, then fragments to registers ----
    #pragma unroll
    for (int it = 0; it < 8; it++) {
        int idx = it*256 + tid;
        int r = idx >> 4, c8 = idx & 15;
        *(uint4*)&qsm[r*PAD16 + c8*8] = *(const uint4*)(qsrc + (size_t)r*C_ + c8*8);
    }
    __syncthreads();

    uint32_t qa[8][4];
    {
        int row = q0 + (lane & 7) + ((lane >> 3) & 1)*8;
        int cof = (lane >> 4)*8;
        #pragma unroll
        for (int ks = 0; ks < 8; ks++)
            ldsm_x4(qa[ks], smbase + (uint32_t)(row*PAD16 + ks*16 + cof)*2);
    }
    __syncthreads();

    float o[16][4];
    #pragma unroll
    for (int ct = 0; ct < 16; ct++)
        #pragma unroll
        for (int j = 0; j < 4; j++) o[ct][j] = 0.f;
    float l0 = 0.f, l1 = 0.f;
    const float K2 = 0.08838834764831845f * 1.4426950408889634f; // /sqrt(128)*log2e

    // precomputed lane pieces for ldmatrix addressing
    const int krow_lo = (lane & 7);           // K: row within octet
    const int kcol    = (lane >> 3)*8;        // K: k-offset (elems)
    const int vrow    = (lane & 7) + ((lane >> 3) & 1)*8;  // V: key row within 16
    const int vcol    = (lane >> 4)*8;        // V: channel offset (elems)

    for (int kt = 0; kt < 16; kt++) {
        const __nv_bfloat16* kc = ksrc + (size_t)(kt*64)*C_;
        const __nv_bfloat16* vc = vsrc + (size_t)(kt*64)*C_;
        #pragma unroll
        for (int it = 0; it < 4; it++) {
            int idx = it*256 + tid;
            int r = idx >> 4, c8 = idx & 15;
            *(uint4*)&ksm[r*PAD16 + c8*8] = *(const uint4*)(kc + (size_t)r*C_ + c8*8);
            *(uint4*)&vsm[r*PAD16 + c8*8] = *(const uint4*)(vc + (size_t)r*C_ + c8*8);
        }
        __syncthreads();

        #pragma unroll
        for (int j = 0; j < 4; j++) {
            // ---- S tiles nt=2j, 2j+1 (keys j*16 .. j*16+15) ----
            float ca[4] = {0.f,0.f,0.f,0.f}, cb[4] = {0.f,0.f,0.f,0.f};
            #pragma unroll
            for (int kbk = 0; kbk < 4; kbk++) {
                uint32_t kfa[4], kfb[4];
                ldsm_x4(kfa, smbase +
                    (uint32_t)(((2*j)*8 + krow_lo)*PAD16 + kbk*32 + kcol)*2);
                ldsm_x4(kfb, smbase +
                    (uint32_t)(((2*j+1)*8 + krow_lo)*PAD16 + kbk*32 + kcol)*2);
                mma_bf16(ca, qa[2*kbk],   kfa[0], kfa[1]);
                mma_bf16(ca, qa[2*kbk+1], kfa[2], kfa[3]);
                mma_bf16(cb, qa[2*kbk],   kfb[0], kfb[1]);
                mma_bf16(cb, qa[2*kbk+1], kfb[2], kfb[3]);
            }
            // ---- exp + pack P as A-fragment (registers only) ----
            float pa0 = fast_ex2(ca[0]*K2), pa1 = fast_ex2(ca[1]*K2);
            float pa2 = fast_ex2(ca[2]*K2), pa3 = fast_ex2(ca[3]*K2);
            float pb0 = fast_ex2(cb[0]*K2), pb1 = fast_ex2(cb[1]*K2);
            float pb2 = fast_ex2(cb[2]*K2), pb3 = fast_ex2(cb[3]*K2);
            l0 += (pa0 + pa1) + (pb0 + pb1);
            l1 += (pa2 + pa3) + (pb2 + pb3);
            uint32_t pA[4];
            pA[0] = pack_bf16(pa0, pa1);
            pA[1] = pack_bf16(pa2, pa3);
            pA[2] = pack_bf16(pb0, pb1);
            pA[3] = pack_bf16(pb2, pb3);

            // ---- O += P V for this 16-key step ----
            uint32_t vbase = smbase + VOFF_B +
                (uint32_t)((j*16 + vrow)*PAD16 + vcol)*2;
            #pragma unroll
            for (int u = 0; u < 8; u++) {
                uint32_t vf[4];
                ldsm_x4t(vf, vbase + (uint32_t)(u*16)*2);
                mma_bf16(o[2*u],   pA, vf[0], vf[1]);
                mma_bf16(o[2*u+1], pA, vf[2], vf[3]);
            }
        }
        __syncthreads();
    }

    // ---- normalize ----
    l0 += __shfl_xor_sync(~0u, l0, 1);
    l0 += __shfl_xor_sync(~0u, l0, 2);
    l1 += __shfl_xor_sync(~0u, l1, 1);
    l1 += __shfl_xor_sync(~0u, l1, 2);
    float inv0 = 1.f / l0, inv1 = 1.f / l1;

    // ---- transpose through smem (fp32), coalesced store ----
    #pragma unroll
    for (int ct = 0; ct < 16; ct++) {
        int c = ct*8 + 2*t;
        *(float2*)&osm[(q0 + g)*132 + c]     = make_float2(o[ct][0]*inv0, o[ct][1]*inv0);
        *(float2*)&osm[(q0 + g + 8)*132 + c] = make_float2(o[ct][2]*inv1, o[ct][3]*inv1);
    }
    __syncthreads();
    #pragma unroll
    for (int it = 0; it < 64; it++) {
        int idx = it*256 + tid;
        int c = idx >> 7, q = idx & 127;
        out[(size_t)c*HW_ + qt*128 + q] = osm[q*132 + c];
    }
}

// ---------------------------------------------------------------------------
// Output projection via tf32 mma (unchanged from R4)
// ---------------------------------------------------------------------------
__global__ void __launch_bounds__(256, 1) out_mma_kernel(
    const float* __restrict__ hh, const float* __restrict__ W3,
    const float* __restrict__ b3, const float* __restrict__ x,
    float* __restrict__ out)
{
    extern __shared__ uint32_t osm2[];
    uint32_t* As = osm2;
    uint32_t* Bs = osm2 + 64*136;

    int pt = blockIdx.x;
    int b  = blockIdx.y;
    const float* hb = hh + (size_t)b*768*HW_;

    const int tid  = threadIdx.x;
    const int warp = tid >> 5;
    const int lane = tid & 31;
    const int g    = lane >> 2;
    const int t    = lane & 3;
    const int q0   = warp * 16;

    float o[16][4];
    #pragma unroll
    for (int ct = 0; ct < 16; ct++)
        #pragma unroll
        for (int j = 0; j < 4; j++) o[ct][j] = 0.f;

    for (int k0 = 0; k0 < 768; k0 += 64) {
        #pragma unroll
        for (int it = 0; it < 8; it++) {
            int idx = it*256 + tid;
            int kk = idx >> 5, n4 = idx & 31;
            float4 hv = *(const float4*)(hb + (size_t)(k0 + kk)*HW_ + pt*128 + n4*4);
            *(uint4*)&Bs[kk*136 + n4*4] =
                make_uint4(f2tf(hv.x), f2tf(hv.y), f2tf(hv.z), f2tf(hv.w));
            float4 wv = *(const float4*)(W3 + (size_t)(k0 + kk)*128 + n4*4);
            *(uint4*)&As[kk*136 + n4*4] =
                make_uint4(f2tf(wv.x), f2tf(wv.y), f2tf(wv.z), f2tf(wv.w));
        }
        __syncthreads();

        #pragma unroll
        for (int ks = 0; ks < 8; ks++) {
            uint32_t a[4];
            int r0 = (ks*8 + t)*136, r1 = (ks*8 + t + 4)*136;
            a[0] = As[r0 + q0 + g];
            a[1] = As[r0 + q0 + g + 8];
            a[2] = As[r1 + q0 + g];
            a[3] = As[r1 + q0 + g + 8];
            #pragma unroll
            for (int ct = 0; ct < 16; ct++) {
                uint32_t bv0 = Bs[(ks*8 + t)*136 + ct*8 + g];
                uint32_t bv1 = Bs[(ks*8 + t + 4)*136 + ct*8 + g];
                mma1688(o[ct], a, bv0, bv1);
            }
        }
        __syncthreads();
    }

    float bb0 = b3[q0 + g];
    float bb1 = b3[q0 + g + 8];
    #pragma unroll
    for (int ct = 0; ct < 16; ct++) {
        size_t a0 = ((size_t)b*C_ + q0 + g)*HW_ + pt*128 + ct*8 + 2*t;
        size_t a1 = ((size_t)b*C_ + q0 + g + 8)*HW_ + pt*128 + ct*8 + 2*t;
        float2 x0 = *(const float2*)&x[a0];
        float2 x1 = *(const float2*)&x[a1];
        *(float2*)&out[a0] = make_float2(o[ct][0] + bb0 + x0.x, o[ct][1] + bb0 + x0.y);
        *(float2*)&out[a1] = make_float2(o[ct][2] + bb1 + x1.x, o[ct][3] + bb1 + x1.y);
    }
}

// ---------------------------------------------------------------------------
extern "C" void kernel_launch(void* const* d_in, const int* in_sizes, int n_in,
                              void* d_out, int out_size)
{
    const float* x      = (const float*)d_in[0];
    const float* q_cond = (const float*)d_in[1];
    const float* ka     = (const float*)d_in[2];
    const float* kb     = (const float*)d_in[3];
    const float* gs     = (const float*)d_in[4];
    const float* gb     = (const float*)d_in[5];
    const float* W0 = (const float*)d_in[6];  const float* b0 = (const float*)d_in[7];
    const float* W1 = (const float*)d_in[8];  const float* b1 = (const float*)d_in[9];
    const float* W2 = (const float*)d_in[10]; const float* b2 = (const float*)d_in[11];
    const float* W3 = (const float*)d_in[12]; const float* b3 = (const float*)d_in[13];
    float* out = (float*)d_out;

    float *h, *hh;
    __nv_bfloat16 *q16, *k16, *v16;
    cudaGetSymbolAddress((void**)&h,   g_h);
    cudaGetSymbolAddress((void**)&q16, g_q16);
    cudaGetSymbolAddress((void**)&k16, g_k16);
    cudaGetSymbolAddress((void**)&v16, g_v16);
    cudaGetSymbolAddress((void**)&hh,  g_hh);

    cudaFuncSetAttribute(attn_bf16_kernel,
                         cudaFuncAttributeMaxDynamicSharedMemorySize, ATTN_SMEM);
    const int out_smem = 2 * 64 * 136 * (int)sizeof(uint32_t);
    cudaFuncSetAttribute(out_mma_kernel,
                         cudaFuncAttributeMaxDynamicSharedMemorySize, out_smem);

    gn_kernel<<<512, 256>>>(x, gs, gb, h);

    dim3 pg(8, 4, 48);
    proj_mma_kernel<<<pg, 256>>>(h, q_cond, ka, kb,
                                 W0, b0, W1, b1, W2, b2,
                                 q16, k16, v16);

    dim3 ag(8, 96);
    attn_bf16_kernel<<<ag, 256, ATTN_SMEM>>>(q16, k16, v16, hh);

    dim3 og(8, 16);
    out_mma_kernel<<<og, 256, out_smem>>>(hh, W3, b3, x, out);
}

// round 6
// speedup vs baseline: 6.8022x; 1.1159x over previous
#include <cuda_runtime.h>
#include <cuda_bf16.h>
#include <cstdint>

#define B_   16
#define C_   128
#define HW_  1024
#define NH_  4
#define COND_ 32

// Scratch (device globals; no allocations allowed)
__device__ __nv_bfloat16  g_h16 [B_*C_*HW_];        // groupnorm output [b][c][s] bf16
__device__ __nv_bfloat16  g_q16 [B_*NH_*HW_*C_];    // q [b*4+e][s][c] bf16
__device__ __nv_bfloat16  g_k16 [B_*NH_*HW_*C_];    // k bf16
__device__ __nv_bfloat16  g_v16 [B_*NH_*HW_*C_];    // v bf16
__device__ __nv_bfloat16  g_hh16[B_*6*C_*HW_];      // [16][768][1024] bf16

// ---------------------------------------------------------------------------
__device__ __forceinline__ uint32_t smem_u32(const void* p) {
    uint32_t a;
    asm("{ .reg .u64 t; cvta.to.shared.u64 t, %1; cvt.u32.u64 %0, t; }"
        : "=r"(a) : "l"(p));
    return a;
}
__device__ __forceinline__ uint32_t pack_bf16(float lo, float hi) {
    uint32_t r;
    asm("cvt.rn.bf16x2.f32 %0, %1, %2;" : "=r"(r) : "f"(hi), "f"(lo));
    return r;
}
__device__ __forceinline__ float fast_ex2(float x) {
    float y;
    asm("ex2.approx.f32 %0, %1;" : "=f"(y) : "f"(x));
    return y;
}
__device__ __forceinline__ void mma_bf16(float c[4], const uint32_t a[4],
                                         uint32_t b0, uint32_t b1) {
    asm volatile("mma.sync.aligned.m16n8k16.row.col.f32.bf16.bf16.f32 "
        "{%0,%1,%2,%3}, {%4,%5,%6,%7}, {%8,%9}, {%0,%1,%2,%3};"
        : "+f"(c[0]), "+f"(c[1]), "+f"(c[2]), "+f"(c[3])
        : "r"(a[0]), "r"(a[1]), "r"(a[2]), "r"(a[3]), "r"(b0), "r"(b1));
}
__device__ __forceinline__ void ldsm_x4(uint32_t r[4], uint32_t addr) {
    asm volatile("ldmatrix.sync.aligned.m8n8.x4.shared.b16 {%0,%1,%2,%3}, [%4];"
        : "=r"(r[0]), "=r"(r[1]), "=r"(r[2]), "=r"(r[3]) : "r"(addr));
}
__device__ __forceinline__ void ldsm_x4t(uint32_t r[4], uint32_t addr) {
    asm volatile("ldmatrix.sync.aligned.m8n8.x4.trans.shared.b16 {%0,%1,%2,%3}, [%4];"
        : "=r"(r[0]), "=r"(r[1]), "=r"(r[2]), "=r"(r[3]) : "r"(addr));
}

// ---------------------------------------------------------------------------
// GroupNorm -> bf16 output
// ---------------------------------------------------------------------------
__global__ void __launch_bounds__(256) gn_kernel(
    const float* __restrict__ x, const float* __restrict__ scale,
    const float* __restrict__ bias, __nv_bfloat16* __restrict__ h)
{
    int b = blockIdx.x >> 5, grp = blockIdx.x & 31;
    const float* xp = x + (size_t)(b*C_ + grp*4)*HW_;
    __nv_bfloat16* hp = h + (size_t)(b*C_ + grp*4)*HW_;

    float s = 0.f, ss = 0.f;
    for (int i = threadIdx.x; i < 2048; i += 256) {
        float2 v = *(const float2*)&xp[i*2];
        s += v.x + v.y; ss += v.x*v.x + v.y*v.y;
    }
    #pragma unroll
    for (int o = 16; o; o >>= 1) {
        s  += __shfl_xor_sync(~0u, s,  o);
        ss += __shfl_xor_sync(~0u, ss, o);
    }
    __shared__ float sh_s[8], sh_ss[8];
    int w = threadIdx.x >> 5;
    if ((threadIdx.x & 31) == 0) { sh_s[w] = s; sh_ss[w] = ss; }
    __syncthreads();
    if (threadIdx.x < 32) {
        s  = (threadIdx.x < 8) ? sh_s [threadIdx.x] : 0.f;
        ss = (threadIdx.x < 8) ? sh_ss[threadIdx.x] : 0.f;
        #pragma unroll
        for (int o = 4; o; o >>= 1) {
            s  += __shfl_xor_sync(~0u, s,  o);
            ss += __shfl_xor_sync(~0u, ss, o);
        }
        if (threadIdx.x == 0) { sh_s[0] = s; sh_ss[0] = ss; }
    }
    __syncthreads();
    float mean = sh_s[0] * (1.f/4096.f);
    float var  = sh_ss[0] * (1.f/4096.f) - mean*mean;
    float inv  = rsqrtf(var + 1e-6f);
    for (int i = threadIdx.x*2; i < 4096; i += 512) {
        int c = grp*4 + (i >> 10);
        float sc = scale[c], bi = bias[c];
        float2 v = *(const float2*)&xp[i];
        uint32_t pk = pack_bf16((v.x - mean)*inv*sc + bi,
                                (v.y - mean)*inv*sc + bi);
        *(uint32_t*)&hp[i] = pk;
    }
}

// ---------------------------------------------------------------------------
// QKV projection via bf16 mma + ldmatrix.
// Block: M = spatial (128, pt tile), N = channels (head e, 128), K = 160
// in 5 chunks of 32. X from bf16 h (chunks 0-3) / fp32 cond (chunk 4).
// ---------------------------------------------------------------------------
__global__ void __launch_bounds__(256, 2) proj_bf16_kernel(
    const __nv_bfloat16* __restrict__ h, const float* __restrict__ q_cond,
    const float* __restrict__ ka, const float* __restrict__ kb,
    const float* __restrict__ W0, const float* __restrict__ b0,
    const float* __restrict__ W1, const float* __restrict__ b1,
    const float* __restrict__ W2, const float* __restrict__ b2,
    __nv_bfloat16* __restrict__ q16, __nv_bfloat16* __restrict__ k16,
    __nv_bfloat16* __restrict__ v16)
{
    int pt = blockIdx.x;          // spatial tile (8)
    int e  = blockIdx.y;          // head (4)
    int b  = blockIdx.z / 3, pr = blockIdx.z % 3;

    const float* W; const float* bias; const float* cond; __nv_bfloat16* dstb;
    if (pr == 0) { W = W0; bias = b0; dstb = q16; cond = q_cond + (size_t)(b>>1)*COND_*HW_; }
    else {
        cond = (((b & 1) ? kb : ka)) + (size_t)(b>>1)*COND_*HW_;
        if (pr == 1) { W = W1; bias = b1; dstb = k16; }
        else         { W = W2; bias = b2; dstb = v16; }
    }
    const __nv_bfloat16* hb = h + (size_t)b*C_*HW_;
    __nv_bfloat16* dst = dstb + (size_t)(b*NH_ + e)*HW_*C_;

    __shared__ __nv_bfloat16 Xs[32*136];
    __shared__ __nv_bfloat16 Ws[32*136];
    const uint32_t xs_base = smem_u32(Xs);
    const uint32_t ws_base = smem_u32(Ws);

    const int tid  = threadIdx.x;
    const int warp = tid >> 5;
    const int lane = tid & 31;
    const int g    = lane >> 2;
    const int t    = lane & 3;
    const int q0   = warp * 16;   // spatial rows within tile

    // ldmatrix lane addressing (trans patterns)
    const int arow = (lane & 7) + ((lane >> 4) & 1)*8;   // + ks*16 (k-index)
    const int acol = q0 + ((lane >> 3) & 1)*8;           // m (spatial)
    const int brow = (lane & 7) + ((lane >> 3) & 1)*8;   // + ks*16 (k-index)
    const int bcol = (lane >> 4)*8;                      // + u*16 (n = channel)

    float o[16][4];
    #pragma unroll
    for (int ct = 0; ct < 16; ct++)
        #pragma unroll
        for (int j = 0; j < 4; j++) o[ct][j] = 0.f;

    for (int ch = 0; ch < 5; ch++) {
        int k0 = ch*32;
        // ---- stage X chunk [32][128] into Xs ----
        if (ch < 4) {
            const __nv_bfloat16* xb = hb + (size_t)k0*HW_ + pt*128;
            #pragma unroll
            for (int it = 0; it < 2; it++) {
                int idx = it*256 + tid;
                int r = idx >> 4, c8 = idx & 15;
                *(uint4*)&Xs[r*136 + c8*8] = *(const uint4*)(xb + (size_t)r*HW_ + c8*8);
            }
        } else {
            const float* cb = cond + pt*128;
            #pragma unroll
            for (int it = 0; it < 4; it++) {
                int idx = it*256 + tid;
                int r = idx >> 5, c4 = idx & 31;
                float4 v = *(const float4*)(cb + (size_t)r*HW_ + c4*4);
                *(uint2*)&Xs[r*136 + c4*4] =
                    make_uint2(pack_bf16(v.x, v.y), pack_bf16(v.z, v.w));
            }
        }
        // ---- stage W chunk [32][128] into Ws ----
        {
            const float* wb = W + (size_t)k0*512 + e*128;
            #pragma unroll
            for (int it = 0; it < 4; it++) {
                int idx = it*256 + tid;
                int r = idx >> 5, c4 = idx & 31;
                float4 v = *(const float4*)(wb + (size_t)r*512 + c4*4);
                *(uint2*)&Ws[r*136 + c4*4] =
                    make_uint2(pack_bf16(v.x, v.y), pack_bf16(v.z, v.w));
            }
        }
        __syncthreads();

        uint32_t a[2][4];
        #pragma unroll
        for (int ks = 0; ks < 2; ks++)
            ldsm_x4t(a[ks], xs_base + (uint32_t)((ks*16 + arow)*136 + acol)*2);
        #pragma unroll
        for (int ks = 0; ks < 2; ks++) {
            #pragma unroll
            for (int u = 0; u < 8; u++) {
                uint32_t bf[4];
                ldsm_x4t(bf, ws_base + (uint32_t)((ks*16 + brow)*136 + u*16 + bcol)*2);
                mma_bf16(o[2*u],   a[ks], bf[0], bf[1]);
                mma_bf16(o[2*u+1], a[ks], bf[2], bf[3]);
            }
        }
        __syncthreads();
    }

    int s_row = pt*128 + q0 + g;
    #pragma unroll
    for (int ct = 0; ct < 16; ct++) {
        int c = ct*8 + 2*t;
        float bL = bias[e*128 + c], bH = bias[e*128 + c + 1];
        uint32_t p0 = pack_bf16(o[ct][0] + bL, o[ct][1] + bH);
        uint32_t p1 = pack_bf16(o[ct][2] + bL, o[ct][3] + bH);
        *(uint32_t*)&dst[(size_t)s_row*C_ + c]       = p0;
        *(uint32_t*)&dst[(size_t)(s_row + 8)*C_ + c] = p1;
    }
}

// ---------------------------------------------------------------------------
// Attention via bf16 mma.sync (m16n8k16) + ldmatrix. P stays in registers.
// hh output now bf16.
// ---------------------------------------------------------------------------
#define PAD16 136
#define VOFF_B 17408
#define ATTN_SMEM 67584

__global__ void __launch_bounds__(256, 2) attn_bf16_kernel(
    const __nv_bfloat16* __restrict__ gq, const __nv_bfloat16* __restrict__ gk,
    const __nv_bfloat16* __restrict__ gv, __nv_bfloat16* __restrict__ hh)
{
    extern __shared__ char smraw[];
    __nv_bfloat16* qsm = (__nv_bfloat16*)smraw;            // [128][136]
    __nv_bfloat16* ksm = (__nv_bfloat16*)smraw;            // [64][136]
    __nv_bfloat16* vsm = (__nv_bfloat16*)(smraw + VOFF_B); // [64][136]
    float*         osm = (float*)smraw;                    // [128][132]
    const uint32_t smbase = smem_u32(smraw);

    const int tid  = threadIdx.x;
    const int warp = tid >> 5;
    const int lane = tid & 31;
    const int g    = lane >> 2;
    const int t    = lane & 3;
    const int q0   = warp * 16;

    int qt = blockIdx.x;
    int z  = blockIdx.y;
    int e  = z & 3, s5 = (z >> 2) % 6, b4 = z / 24;
    const int qtab[6] = {0,1,2,3,0,2};
    const int ktab[6] = {1,0,3,2,2,0};

    const __nv_bfloat16* qsrc = gq + (size_t)((b4*4 + qtab[s5])*NH_ + e)*(HW_*C_)
                                   + (size_t)qt*128*C_;
    const __nv_bfloat16* ksrc = gk + (size_t)((b4*4 + ktab[s5])*NH_ + e)*(HW_*C_);
    const __nv_bfloat16* vsrc = gv + (size_t)((b4*4 + ktab[s5])*NH_ + e)*(HW_*C_);
    int idx0 = s5*512 + e*128;
    __nv_bfloat16* out = hh + ((size_t)(b4*4 + idx0/768)*768 + (idx0 % 768)) * HW_;

    // ---- stage Q [128][136] bf16, then fragments to registers ----
    #pragma unroll
    for (int it = 0; it < 8; it++) {
        int idx = it*256 + tid;
        int r = idx >> 4, c8 = idx & 15;
        *(uint4*)&qsm[r*PAD16 + c8*8] = *(const uint4*)(qsrc + (size_t)r*C_ + c8*8);
    }
    __syncthreads();

    uint32_t qa[8][4];
    {
        int row = q0 + (lane & 7) + ((lane >> 3) & 1)*8;
        int cof = (lane >> 4)*8;
        #pragma unroll
        for (int ks = 0; ks < 8; ks++)
            ldsm_x4(qa[ks], smbase + (uint32_t)(row*PAD16 + ks*16 + cof)*2);
    }
    __syncthreads();

    float o[16][4];
    #pragma unroll
    for (int ct = 0; ct < 16; ct++)
        #pragma unroll
        for (int j = 0; j < 4; j++) o[ct][j] = 0.f;
    float l0 = 0.f, l1 = 0.f;
    const float K2 = 0.08838834764831845f * 1.4426950408889634f;

    const int krow_lo = (lane & 7);
    const int kcol    = (lane >> 3)*8;
    const int vrow    = (lane & 7) + ((lane >> 3) & 1)*8;
    const int vcol    = (lane >> 4)*8;

    for (int kt = 0; kt < 16; kt++) {
        const __nv_bfloat16* kc = ksrc + (size_t)(kt*64)*C_;
        const __nv_bfloat16* vc = vsrc + (size_t)(kt*64)*C_;
        #pragma unroll
        for (int it = 0; it < 4; it++) {
            int idx = it*256 + tid;
            int r = idx >> 4, c8 = idx & 15;
            *(uint4*)&ksm[r*PAD16 + c8*8] = *(const uint4*)(kc + (size_t)r*C_ + c8*8);
            *(uint4*)&vsm[r*PAD16 + c8*8] = *(const uint4*)(vc + (size_t)r*C_ + c8*8);
        }
        __syncthreads();

        #pragma unroll
        for (int j = 0; j < 4; j++) {
            float ca[4] = {0.f,0.f,0.f,0.f}, cb[4] = {0.f,0.f,0.f,0.f};
            #pragma unroll
            for (int kbk = 0; kbk < 4; kbk++) {
                uint32_t kfa[4], kfb[4];
                ldsm_x4(kfa, smbase +
                    (uint32_t)(((2*j)*8 + krow_lo)*PAD16 + kbk*32 + kcol)*2);
                ldsm_x4(kfb, smbase +
                    (uint32_t)(((2*j+1)*8 + krow_lo)*PAD16 + kbk*32 + kcol)*2);
                mma_bf16(ca, qa[2*kbk],   kfa[0], kfa[1]);
                mma_bf16(ca, qa[2*kbk+1], kfa[2], kfa[3]);
                mma_bf16(cb, qa[2*kbk],   kfb[0], kfb[1]);
                mma_bf16(cb, qa[2*kbk+1], kfb[2], kfb[3]);
            }
            float pa0 = fast_ex2(ca[0]*K2), pa1 = fast_ex2(ca[1]*K2);
            float pa2 = fast_ex2(ca[2]*K2), pa3 = fast_ex2(ca[3]*K2);
            float pb0 = fast_ex2(cb[0]*K2), pb1 = fast_ex2(cb[1]*K2);
            float pb2 = fast_ex2(cb[2]*K2), pb3 = fast_ex2(cb[3]*K2);
            l0 += (pa0 + pa1) + (pb0 + pb1);
            l1 += (pa2 + pa3) + (pb2 + pb3);
            uint32_t pA[4];
            pA[0] = pack_bf16(pa0, pa1);
            pA[1] = pack_bf16(pa2, pa3);
            pA[2] = pack_bf16(pb0, pb1);
            pA[3] = pack_bf16(pb2, pb3);

            uint32_t vbase = smbase + VOFF_B +
                (uint32_t)((j*16 + vrow)*PAD16 + vcol)*2;
            #pragma unroll
            for (int u = 0; u < 8; u++) {
                uint32_t vf[4];
                ldsm_x4t(vf, vbase + (uint32_t)(u*16)*2);
                mma_bf16(o[2*u],   pA, vf[0], vf[1]);
                mma_bf16(o[2*u+1], pA, vf[2], vf[3]);
            }
        }
        __syncthreads();
    }

    l0 += __shfl_xor_sync(~0u, l0, 1);
    l0 += __shfl_xor_sync(~0u, l0, 2);
    l1 += __shfl_xor_sync(~0u, l1, 1);
    l1 += __shfl_xor_sync(~0u, l1, 2);
    float inv0 = 1.f / l0, inv1 = 1.f / l1;

    #pragma unroll
    for (int ct = 0; ct < 16; ct++) {
        int c = ct*8 + 2*t;
        *(float2*)&osm[(q0 + g)*132 + c]     = make_float2(o[ct][0]*inv0, o[ct][1]*inv0);
        *(float2*)&osm[(q0 + g + 8)*132 + c] = make_float2(o[ct][2]*inv1, o[ct][3]*inv1);
    }
    __syncthreads();
    #pragma unroll
    for (int it = 0; it < 32; it++) {
        int idx = it*256 + tid;
        int c = idx >> 6, qp = idx & 63;
        uint32_t pk = pack_bf16(osm[(2*qp)*132 + c], osm[(2*qp + 1)*132 + c]);
        *(uint32_t*)&out[(size_t)c*HW_ + qt*128 + 2*qp] = pk;
    }
}

// ---------------------------------------------------------------------------
// Output projection via bf16 mma + ldmatrix. M=128 channels, N=128 spatial,
// K=768 in 12 chunks of 64. A = W3 (fp32->bf16), B = hh bf16.
// ---------------------------------------------------------------------------
__global__ void __launch_bounds__(256) out_bf16_kernel(
    const __nv_bfloat16* __restrict__ hh, const float* __restrict__ W3,
    const float* __restrict__ b3, const float* __restrict__ x,
    float* __restrict__ out)
{
    extern __shared__ __nv_bfloat16 sm2[];
    __nv_bfloat16* As = sm2;             // [64][136]
    __nv_bfloat16* Bs = sm2 + 64*136;    // [64][136]
    const uint32_t as_base = smem_u32(As);
    const uint32_t bs_base = smem_u32(Bs);

    int pt = blockIdx.x;   // 8
    int b  = blockIdx.y;   // 16
    const __nv_bfloat16* hb = hh + (size_t)b*768*HW_;

    const int tid  = threadIdx.x;
    const int warp = tid >> 5;
    const int lane = tid & 31;
    const int g    = lane >> 2;
    const int t    = lane & 3;
    const int q0   = warp * 16;   // channel rows

    const int arow = (lane & 7) + ((lane >> 4) & 1)*8;
    const int acol = q0 + ((lane >> 3) & 1)*8;
    const int brow = (lane & 7) + ((lane >> 3) & 1)*8;
    const int bcol = (lane >> 4)*8;

    float o[16][4];
    #pragma unroll
    for (int ct = 0; ct < 16; ct++)
        #pragma unroll
        for (int j = 0; j < 4; j++) o[ct][j] = 0.f;

    for (int k0 = 0; k0 < 768; k0 += 64) {
        #pragma unroll
        for (int it = 0; it < 8; it++) {
            int idx = it*256 + tid;
            int r = idx >> 5, c4 = idx & 31;
            float4 wv = *(const float4*)(W3 + (size_t)(k0 + r)*128 + c4*4);
            *(uint2*)&As[r*136 + c4*4] =
                make_uint2(pack_bf16(wv.x, wv.y), pack_bf16(wv.z, wv.w));
        }
        #pragma unroll
        for (int it = 0; it < 4; it++) {
            int idx = it*256 + tid;
            int r = idx >> 4, c8 = idx & 15;
            *(uint4*)&Bs[r*136 + c8*8] =
                *(const uint4*)(hb + (size_t)(k0 + r)*HW_ + pt*128 + c8*8);
        }
        __syncthreads();

        uint32_t a[4][4];
        #pragma unroll
        for (int ks = 0; ks < 4; ks++)
            ldsm_x4t(a[ks], as_base + (uint32_t)((ks*16 + arow)*136 + acol)*2);
        #pragma unroll
        for (int ks = 0; ks < 4; ks++) {
            #pragma unroll
            for (int u = 0; u < 8; u++) {
                uint32_t bf[4];
                ldsm_x4t(bf, bs_base + (uint32_t)((ks*16 + brow)*136 + u*16 + bcol)*2);
                mma_bf16(o[2*u],   a[ks], bf[0], bf[1]);
                mma_bf16(o[2*u+1], a[ks], bf[2], bf[3]);
            }
        }
        __syncthreads();
    }

    float bb0 = b3[q0 + g];
    float bb1 = b3[q0 + g + 8];
    #pragma unroll
    for (int ct = 0; ct < 16; ct++) {
        size_t a0 = ((size_t)b*C_ + q0 + g)*HW_ + pt*128 + ct*8 + 2*t;
        size_t a1 = ((size_t)b*C_ + q0 + g + 8)*HW_ + pt*128 + ct*8 + 2*t;
        float2 x0 = *(const float2*)&x[a0];
        float2 x1 = *(const float2*)&x[a1];
        *(float2*)&out[a0] = make_float2(o[ct][0] + bb0 + x0.x, o[ct][1] + bb0 + x0.y);
        *(float2*)&out[a1] = make_float2(o[ct][2] + bb1 + x1.x, o[ct][3] + bb1 + x1.y);
    }
}

// ---------------------------------------------------------------------------
extern "C" void kernel_launch(void* const* d_in, const int* in_sizes, int n_in,
                              void* d_out, int out_size)
{
    const float* x      = (const float*)d_in[0];
    const float* q_cond = (const float*)d_in[1];
    const float* ka     = (const float*)d_in[2];
    const float* kb     = (const float*)d_in[3];
    const float* gs     = (const float*)d_in[4];
    const float* gb     = (const float*)d_in[5];
    const float* W0 = (const float*)d_in[6];  const float* b0 = (const float*)d_in[7];
    const float* W1 = (const float*)d_in[8];  const float* b1 = (const float*)d_in[9];
    const float* W2 = (const float*)d_in[10]; const float* b2 = (const float*)d_in[11];
    const float* W3 = (const float*)d_in[12]; const float* b3 = (const float*)d_in[13];
    float* out = (float*)d_out;

    __nv_bfloat16 *h16, *q16, *k16, *v16, *hh16;
    cudaGetSymbolAddress((void**)&h16,  g_h16);
    cudaGetSymbolAddress((void**)&q16,  g_q16);
    cudaGetSymbolAddress((void**)&k16,  g_k16);
    cudaGetSymbolAddress((void**)&v16,  g_v16);
    cudaGetSymbolAddress((void**)&hh16, g_hh16);

    cudaFuncSetAttribute(attn_bf16_kernel,
                         cudaFuncAttributeMaxDynamicSharedMemorySize, ATTN_SMEM);
    const int out_smem = 2 * 64 * 136 * 2;  // 34816 B
    cudaFuncSetAttribute(out_bf16_kernel,
                         cudaFuncAttributeMaxDynamicSharedMemorySize, out_smem);

    gn_kernel<<<512, 256>>>(x, gs, gb, h16);

    dim3 pg(8, 4, 48);
    proj_bf16_kernel<<<pg, 256>>>(h16, q_cond, ka, kb,
                                  W0, b0, W1, b1, W2, b2,
                                  q16, k16, v16);

    dim3 ag(8, 96);
    attn_bf16_kernel<<<ag, 256, ATTN_SMEM>>>(q16, k16, v16, hh16);

    dim3 og(8, 16);
    out_bf16_kernel<<<og, 256, out_smem>>>(hh16, W3, b3, x, out);
}

// round 7
// speedup vs baseline: 7.8446x; 1.1532x over previous
#include <cuda_runtime.h>
#include <cuda_bf16.h>
#include <cstdint>

#define B_   16
#define C_   128
#define HW_  1024
#define NH_  4
#define COND_ 32

// Scratch (device globals; no allocations allowed)
__device__ __nv_bfloat16  g_h16 [B_*C_*HW_];        // groupnorm output [b][c][s]
__device__ __nv_bfloat16  g_q16 [B_*NH_*HW_*C_];    // q [b*4+e][s][c]
__device__ __nv_bfloat16  g_k16 [B_*NH_*HW_*C_];
__device__ __nv_bfloat16  g_v16 [B_*NH_*HW_*C_];
__device__ __nv_bfloat16  g_hh16[B_*6*C_*HW_];      // [16][768][1024]
// bf16 weight/cond copies (converted once per call)
__device__ __nv_bfloat16  g_w0b[160*512];
__device__ __nv_bfloat16  g_w1b[160*512];
__device__ __nv_bfloat16  g_w2b[160*512];
__device__ __nv_bfloat16  g_w3b[768*128];
__device__ __nv_bfloat16  g_qcb[(B_/2)*COND_*HW_];
__device__ __nv_bfloat16  g_kab[(B_/2)*COND_*HW_];
__device__ __nv_bfloat16  g_kbb[(B_/2)*COND_*HW_];

// ---------------------------------------------------------------------------
__device__ __forceinline__ uint32_t smem_u32(const void* p) {
    uint32_t a;
    asm("{ .reg .u64 t; cvta.to.shared.u64 t, %1; cvt.u32.u64 %0, t; }"
        : "=r"(a) : "l"(p));
    return a;
}
__device__ __forceinline__ uint32_t pack_bf16(float lo, float hi) {
    uint32_t r;
    asm("cvt.rn.bf16x2.f32 %0, %1, %2;" : "=r"(r) : "f"(hi), "f"(lo));
    return r;
}
__device__ __forceinline__ float fast_ex2(float x) {
    float y;
    asm("ex2.approx.f32 %0, %1;" : "=f"(y) : "f"(x));
    return y;
}
__device__ __forceinline__ void mma_bf16(float c[4], const uint32_t a[4],
                                         uint32_t b0, uint32_t b1) {
    asm volatile("mma.sync.aligned.m16n8k16.row.col.f32.bf16.bf16.f32 "
        "{%0,%1,%2,%3}, {%4,%5,%6,%7}, {%8,%9}, {%0,%1,%2,%3};"
        : "+f"(c[0]), "+f"(c[1]), "+f"(c[2]), "+f"(c[3])
        : "r"(a[0]), "r"(a[1]), "r"(a[2]), "r"(a[3]), "r"(b0), "r"(b1));
}
__device__ __forceinline__ void ldsm_x4(uint32_t r[4], uint32_t addr) {
    asm volatile("ldmatrix.sync.aligned.m8n8.x4.shared.b16 {%0,%1,%2,%3}, [%4];"
        : "=r"(r[0]), "=r"(r[1]), "=r"(r[2]), "=r"(r[3]) : "r"(addr));
}
__device__ __forceinline__ void ldsm_x4t(uint32_t r[4], uint32_t addr) {
    asm volatile("ldmatrix.sync.aligned.m8n8.x4.trans.shared.b16 {%0,%1,%2,%3}, [%4];"
        : "=r"(r[0]), "=r"(r[1]), "=r"(r[2]), "=r"(r[3]) : "r"(addr));
}
__device__ __forceinline__ void cp_async16(uint32_t dst, const void* src) {
    asm volatile("cp.async.cg.shared.global [%0], [%1], 16;"
                 :: "r"(dst), "l"(src) : "memory");
}
#define CP_COMMIT() asm volatile("cp.async.commit_group;" ::: "memory")
#define CP_WAIT1()  asm volatile("cp.async.wait_group 1;" ::: "memory")
#define CP_WAIT0()  asm volatile("cp.async.wait_group 0;" ::: "memory")

// ---------------------------------------------------------------------------
// fp32 -> bf16 conversion of weights + cond tensors (once per call)
// ---------------------------------------------------------------------------
__global__ void __launch_bounds__(256) cvt_kernel(
    const float* __restrict__ W0, const float* __restrict__ W1,
    const float* __restrict__ W2, const float* __restrict__ W3,
    const float* __restrict__ qc, const float* __restrict__ ka,
    const float* __restrict__ kb)
{
    const float* src; __nv_bfloat16* dst; int n;
    switch (blockIdx.y) {
        case 0: src = W0; dst = g_w0b; n = 160*512;          break;
        case 1: src = W1; dst = g_w1b; n = 160*512;          break;
        case 2: src = W2; dst = g_w2b; n = 160*512;          break;
        case 3: src = W3; dst = g_w3b; n = 768*128;          break;
        case 4: src = qc; dst = g_qcb; n = (B_/2)*COND_*HW_; break;
        case 5: src = ka; dst = g_kab; n = (B_/2)*COND_*HW_; break;
        default: src = kb; dst = g_kbb; n = (B_/2)*COND_*HW_; break;
    }
    for (int i = (blockIdx.x*256 + threadIdx.x)*4; i < n; i += 256*256*4) {
        float4 v = *(const float4*)&src[i];
        *(uint2*)&dst[i] = make_uint2(pack_bf16(v.x, v.y), pack_bf16(v.z, v.w));
    }
}

// ---------------------------------------------------------------------------
// GroupNorm -> bf16
// ---------------------------------------------------------------------------
__global__ void __launch_bounds__(256) gn_kernel(
    const float* __restrict__ x, const float* __restrict__ scale,
    const float* __restrict__ bias, __nv_bfloat16* __restrict__ h)
{
    int b = blockIdx.x >> 5, grp = blockIdx.x & 31;
    const float* xp = x + (size_t)(b*C_ + grp*4)*HW_;
    __nv_bfloat16* hp = h + (size_t)(b*C_ + grp*4)*HW_;

    float s = 0.f, ss = 0.f;
    for (int i = threadIdx.x; i < 2048; i += 256) {
        float2 v = *(const float2*)&xp[i*2];
        s += v.x + v.y; ss += v.x*v.x + v.y*v.y;
    }
    #pragma unroll
    for (int o = 16; o; o >>= 1) {
        s  += __shfl_xor_sync(~0u, s,  o);
        ss += __shfl_xor_sync(~0u, ss, o);
    }
    __shared__ float sh_s[8], sh_ss[8];
    int w = threadIdx.x >> 5;
    if ((threadIdx.x & 31) == 0) { sh_s[w] = s; sh_ss[w] = ss; }
    __syncthreads();
    if (threadIdx.x < 32) {
        s  = (threadIdx.x < 8) ? sh_s [threadIdx.x] : 0.f;
        ss = (threadIdx.x < 8) ? sh_ss[threadIdx.x] : 0.f;
        #pragma unroll
        for (int o = 4; o; o >>= 1) {
            s  += __shfl_xor_sync(~0u, s,  o);
            ss += __shfl_xor_sync(~0u, ss, o);
        }
        if (threadIdx.x == 0) { sh_s[0] = s; sh_ss[0] = ss; }
    }
    __syncthreads();
    float mean = sh_s[0] * (1.f/4096.f);
    float var  = sh_ss[0] * (1.f/4096.f) - mean*mean;
    float inv  = rsqrtf(var + 1e-6f);
    for (int i = threadIdx.x*2; i < 4096; i += 512) {
        int c = grp*4 + (i >> 10);
        float sc = scale[c], bi = bias[c];
        float2 v = *(const float2*)&xp[i];
        *(uint32_t*)&hp[i] = pack_bf16((v.x - mean)*inv*sc + bi,
                                       (v.y - mean)*inv*sc + bi);
    }
}

// ---------------------------------------------------------------------------
// QKV projection: bf16 mma + ldmatrix + cp.async double-buffered staging.
// Block: M = spatial (128), N = channels (head, 128), K = 160 in 5x32 chunks.
// ---------------------------------------------------------------------------
__global__ void __launch_bounds__(256, 2) proj_bf16_kernel(
    const __nv_bfloat16* __restrict__ h,
    const float* __restrict__ b0, const float* __restrict__ b1,
    const float* __restrict__ b2,
    __nv_bfloat16* __restrict__ q16, __nv_bfloat16* __restrict__ k16,
    __nv_bfloat16* __restrict__ v16)
{
    int pt = blockIdx.x;          // spatial tile (8)
    int e  = blockIdx.y;          // head (4)
    int b  = blockIdx.z / 3, pr = blockIdx.z % 3;

    const __nv_bfloat16* Wb; const float* bias; const __nv_bfloat16* cond;
    __nv_bfloat16* dstb;
    if (pr == 0) { Wb = g_w0b; bias = b0; dstb = q16; cond = g_qcb + (size_t)(b>>1)*COND_*HW_; }
    else {
        cond = (((b & 1) ? g_kbb : g_kab)) + (size_t)(b>>1)*COND_*HW_;
        if (pr == 1) { Wb = g_w1b; bias = b1; dstb = k16; }
        else         { Wb = g_w2b; bias = b2; dstb = v16; }
    }
    const __nv_bfloat16* hb = h + (size_t)b*C_*HW_;
    __nv_bfloat16* dst = dstb + (size_t)(b*NH_ + e)*HW_*C_;

    __shared__ __nv_bfloat16 Xs[2][32*136];
    __shared__ __nv_bfloat16 Ws[2][32*136];
    const uint32_t xs_base0 = smem_u32(&Xs[0][0]);
    const uint32_t xs_base1 = smem_u32(&Xs[1][0]);
    const uint32_t ws_base0 = smem_u32(&Ws[0][0]);
    const uint32_t ws_base1 = smem_u32(&Ws[1][0]);

    const int tid  = threadIdx.x;
    const int warp = tid >> 5;
    const int lane = tid & 31;
    const int g    = lane >> 2;
    const int t    = lane & 3;
    const int q0   = warp * 16;

    const int arow = (lane & 7) + ((lane >> 4) & 1)*8;
    const int acol = q0 + ((lane >> 3) & 1)*8;
    const int brow = (lane & 7) + ((lane >> 3) & 1)*8;
    const int bcol = (lane >> 4)*8;

    auto stage = [&](int ch, int st) {
        uint32_t xd = st ? xs_base1 : xs_base0;
        uint32_t wd = st ? ws_base1 : ws_base0;
        const __nv_bfloat16* xsrc = (ch < 4) ? (hb + (size_t)(ch*32)*HW_ + pt*128)
                                             : (cond + pt*128);
        const __nv_bfloat16* wsrc = Wb + (size_t)(ch*32)*512 + e*128;
        #pragma unroll
        for (int it = 0; it < 2; it++) {
            int idx = it*256 + tid;
            int r = idx >> 4, c8 = idx & 15;
            cp_async16(xd + (uint32_t)(r*136 + c8*8)*2, xsrc + (size_t)r*HW_ + c8*8);
            cp_async16(wd + (uint32_t)(r*136 + c8*8)*2, wsrc + (size_t)r*512 + c8*8);
        }
    };

    float o[16][4];
    #pragma unroll
    for (int ct = 0; ct < 16; ct++)
        #pragma unroll
        for (int j = 0; j < 4; j++) o[ct][j] = 0.f;

    stage(0, 0); CP_COMMIT();

    for (int ch = 0; ch < 5; ch++) {
        int cur = ch & 1;
        if (ch < 4) { stage(ch + 1, cur ^ 1); CP_COMMIT(); CP_WAIT1(); }
        else        { CP_WAIT0(); }
        __syncthreads();

        uint32_t xb = cur ? xs_base1 : xs_base0;
        uint32_t wb2 = cur ? ws_base1 : ws_base0;
        uint32_t a[2][4];
        #pragma unroll
        for (int ks = 0; ks < 2; ks++)
            ldsm_x4t(a[ks], xb + (uint32_t)((ks*16 + arow)*136 + acol)*2);
        #pragma unroll
        for (int ks = 0; ks < 2; ks++) {
            #pragma unroll
            for (int u = 0; u < 8; u++) {
                uint32_t bf[4];
                ldsm_x4t(bf, wb2 + (uint32_t)((ks*16 + brow)*136 + u*16 + bcol)*2);
                mma_bf16(o[2*u],   a[ks], bf[0], bf[1]);
                mma_bf16(o[2*u+1], a[ks], bf[2], bf[3]);
            }
        }
        __syncthreads();
    }

    int s_row = pt*128 + q0 + g;
    #pragma unroll
    for (int ct = 0; ct < 16; ct++) {
        int c = ct*8 + 2*t;
        float bL = bias[e*128 + c], bH = bias[e*128 + c + 1];
        *(uint32_t*)&dst[(size_t)s_row*C_ + c]       = pack_bf16(o[ct][0] + bL, o[ct][1] + bH);
        *(uint32_t*)&dst[(size_t)(s_row + 8)*C_ + c] = pack_bf16(o[ct][2] + bL, o[ct][3] + bH);
    }
}

// ---------------------------------------------------------------------------
// Attention: bf16 mma + ldmatrix + cp.async double-buffered K/V.
// smem: K0 @0, K1 @17408, V0 @34816, V1 @52224 (each [64][136] bf16).
// Q stage + epilogue fp32 [128][132] alias the buffers. Total 69632 B.
// ---------------------------------------------------------------------------
#define PAD16 136
#define KVBUF 17408
#define ATTN_SMEM 69632

__global__ void __launch_bounds__(256, 2) attn_bf16_kernel(
    const __nv_bfloat16* __restrict__ gq, const __nv_bfloat16* __restrict__ gk,
    const __nv_bfloat16* __restrict__ gv, __nv_bfloat16* __restrict__ hh)
{
    extern __shared__ char smraw[];
    __nv_bfloat16* qsm = (__nv_bfloat16*)smraw;   // [128][136] staging
    float*         osm = (float*)smraw;           // [128][132] epilogue
    const uint32_t smbase = smem_u32(smraw);

    const int tid  = threadIdx.x;
    const int warp = tid >> 5;
    const int lane = tid & 31;
    const int g    = lane >> 2;
    const int t    = lane & 3;
    const int q0   = warp * 16;

    int qt = blockIdx.x;
    int z  = blockIdx.y;
    int e  = z & 3, s5 = (z >> 2) % 6, b4 = z / 24;
    const int qtab[6] = {0,1,2,3,0,2};
    const int ktab[6] = {1,0,3,2,2,0};

    const __nv_bfloat16* qsrc = gq + (size_t)((b4*4 + qtab[s5])*NH_ + e)*(HW_*C_)
                                   + (size_t)qt*128*C_;
    const __nv_bfloat16* ksrc = gk + (size_t)((b4*4 + ktab[s5])*NH_ + e)*(HW_*C_);
    const __nv_bfloat16* vsrc = gv + (size_t)((b4*4 + ktab[s5])*NH_ + e)*(HW_*C_);
    int idx0 = s5*512 + e*128;
    __nv_bfloat16* out = hh + ((size_t)(b4*4 + idx0/768)*768 + (idx0 % 768)) * HW_;

    // ---- stage Q, load fragments ----
    #pragma unroll
    for (int it = 0; it < 8; it++) {
        int idx = it*256 + tid;
        int r = idx >> 4, c8 = idx & 15;
        *(uint4*)&qsm[r*PAD16 + c8*8] = *(const uint4*)(qsrc + (size_t)r*C_ + c8*8);
    }
    __syncthreads();
    uint32_t qa[8][4];
    {
        int row = q0 + (lane & 7) + ((lane >> 3) & 1)*8;
        int cof = (lane >> 4)*8;
        #pragma unroll
        for (int ks = 0; ks < 8; ks++)
            ldsm_x4(qa[ks], smbase + (uint32_t)(row*PAD16 + ks*16 + cof)*2);
    }
    __syncthreads();

    auto stage_kv = [&](int kt, int st) {
        const __nv_bfloat16* kc = ksrc + (size_t)(kt*64)*C_;
        const __nv_bfloat16* vc = vsrc + (size_t)(kt*64)*C_;
        uint32_t kd = smbase + st*KVBUF;
        uint32_t vd = smbase + (2 + st)*KVBUF;
        #pragma unroll
        for (int it = 0; it < 4; it++) {
            int idx = it*256 + tid;
            int r = idx >> 4, c8 = idx & 15;
            cp_async16(kd + (uint32_t)(r*PAD16 + c8*8)*2, kc + (size_t)r*C_ + c8*8);
            cp_async16(vd + (uint32_t)(r*PAD16 + c8*8)*2, vc + (size_t)r*C_ + c8*8);
        }
    };

    float o[16][4];
    #pragma unroll
    for (int ct = 0; ct < 16; ct++)
        #pragma unroll
        for (int j = 0; j < 4; j++) o[ct][j] = 0.f;
    float l0 = 0.f, l1 = 0.f;
    const float K2 = 0.08838834764831845f * 1.4426950408889634f;

    const int krow_lo = (lane & 7);
    const int kcol    = (lane >> 3)*8;
    const int vrow    = (lane & 7) + ((lane >> 3) & 1)*8;
    const int vcol    = (lane >> 4)*8;

    stage_kv(0, 0); CP_COMMIT();

    for (int kt = 0; kt < 16; kt++) {
        int cur = kt & 1;
        if (kt < 15) { stage_kv(kt + 1, cur ^ 1); CP_COMMIT(); CP_WAIT1(); }
        else         { CP_WAIT0(); }
        __syncthreads();

        uint32_t kb2 = smbase + cur*KVBUF;
        uint32_t vb2 = smbase + (2 + cur)*KVBUF;

        #pragma unroll
        for (int j = 0; j < 4; j++) {
            float ca[4] = {0.f,0.f,0.f,0.f}, cb[4] = {0.f,0.f,0.f,0.f};
            #pragma unroll
            for (int kbk = 0; kbk < 4; kbk++) {
                uint32_t kfa[4], kfb[4];
                ldsm_x4(kfa, kb2 + (uint32_t)(((2*j)*8 + krow_lo)*PAD16 + kbk*32 + kcol)*2);
                ldsm_x4(kfb, kb2 + (uint32_t)(((2*j+1)*8 + krow_lo)*PAD16 + kbk*32 + kcol)*2);
                mma_bf16(ca, qa[2*kbk],   kfa[0], kfa[1]);
                mma_bf16(ca, qa[2*kbk+1], kfa[2], kfa[3]);
                mma_bf16(cb, qa[2*kbk],   kfb[0], kfb[1]);
                mma_bf16(cb, qa[2*kbk+1], kfb[2], kfb[3]);
            }
            float pa0 = fast_ex2(ca[0]*K2), pa1 = fast_ex2(ca[1]*K2);
            float pa2 = fast_ex2(ca[2]*K2), pa3 = fast_ex2(ca[3]*K2);
            float pb0 = fast_ex2(cb[0]*K2), pb1 = fast_ex2(cb[1]*K2);
            float pb2 = fast_ex2(cb[2]*K2), pb3 = fast_ex2(cb[3]*K2);
            l0 += (pa0 + pa1) + (pb0 + pb1);
            l1 += (pa2 + pa3) + (pb2 + pb3);
            uint32_t pA[4];
            pA[0] = pack_bf16(pa0, pa1);
            pA[1] = pack_bf16(pa2, pa3);
            pA[2] = pack_bf16(pb0, pb1);
            pA[3] = pack_bf16(pb2, pb3);

            uint32_t vbase = vb2 + (uint32_t)((j*16 + vrow)*PAD16 + vcol)*2;
            #pragma unroll
            for (int u = 0; u < 8; u++) {
                uint32_t vf[4];
                ldsm_x4t(vf, vbase + (uint32_t)(u*16)*2);
                mma_bf16(o[2*u],   pA, vf[0], vf[1]);
                mma_bf16(o[2*u+1], pA, vf[2], vf[3]);
            }
        }
        __syncthreads();
    }

    l0 += __shfl_xor_sync(~0u, l0, 1);
    l0 += __shfl_xor_sync(~0u, l0, 2);
    l1 += __shfl_xor_sync(~0u, l1, 1);
    l1 += __shfl_xor_sync(~0u, l1, 2);
    float inv0 = 1.f / l0, inv1 = 1.f / l1;

    #pragma unroll
    for (int ct = 0; ct < 16; ct++) {
        int c = ct*8 + 2*t;
        *(float2*)&osm[(q0 + g)*132 + c]     = make_float2(o[ct][0]*inv0, o[ct][1]*inv0);
        *(float2*)&osm[(q0 + g + 8)*132 + c] = make_float2(o[ct][2]*inv1, o[ct][3]*inv1);
    }
    __syncthreads();
    #pragma unroll
    for (int it = 0; it < 32; it++) {
        int idx = it*256 + tid;
        int c = idx >> 6, qp = idx & 63;
        uint32_t pk = pack_bf16(osm[(2*qp)*132 + c], osm[(2*qp + 1)*132 + c]);
        *(uint32_t*)&out[(size_t)c*HW_ + qt*128 + 2*qp] = pk;
    }
}

// ---------------------------------------------------------------------------
// Output projection: bf16 mma + ldmatrix + cp.async double buffering.
// M=128 channels, N=128 spatial, K=768 in 12x64 chunks. Fused bias + skip.
// smem layout (bf16 elems): A0 @0, A1 @8704, B0 @17408, B1 @26112.
// ---------------------------------------------------------------------------
__global__ void __launch_bounds__(256) out_bf16_kernel(
    const __nv_bfloat16* __restrict__ hh, const float* __restrict__ b3,
    const float* __restrict__ x, float* __restrict__ out)
{
    extern __shared__ __nv_bfloat16 sm2[];
    const uint32_t base = smem_u32(sm2);

    int pt = blockIdx.x;   // 8
    int b  = blockIdx.y;   // 16
    const __nv_bfloat16* hb = hh + (size_t)b*768*HW_;

    const int tid  = threadIdx.x;
    const int warp = tid >> 5;
    const int lane = tid & 31;
    const int g    = lane >> 2;
    const int t    = lane & 3;
    const int q0   = warp * 16;

    const int arow = (lane & 7) + ((lane >> 4) & 1)*8;
    const int acol = q0 + ((lane >> 3) & 1)*8;
    const int brow = (lane & 7) + ((lane >> 3) & 1)*8;
    const int bcol = (lane >> 4)*8;

    auto stage = [&](int kc, int st) {
        uint32_t ad = base + (uint32_t)(st*8704)*2;
        uint32_t bd = base + (uint32_t)((2 + st)*8704)*2;
        const __nv_bfloat16* asrc = g_w3b + (size_t)(kc*64)*128;
        const __nv_bfloat16* bsrc = hb + (size_t)(kc*64)*HW_ + pt*128;
        #pragma unroll
        for (int it = 0; it < 4; it++) {
            int idx = it*256 + tid;
            int r = idx >> 4, c8 = idx & 15;
            cp_async16(ad + (uint32_t)(r*136 + c8*8)*2, asrc + (size_t)r*128 + c8*8);
            cp_async16(bd + (uint32_t)(r*136 + c8*8)*2, bsrc + (size_t)r*HW_ + c8*8);
        }
    };

    float o[16][4];
    #pragma unroll
    for (int ct = 0; ct < 16; ct++)
        #pragma unroll
        for (int j = 0; j < 4; j++) o[ct][j] = 0.f;

    stage(0, 0); CP_COMMIT();

    for (int kc = 0; kc < 12; kc++) {
        int cur = kc & 1;
        if (kc < 11) { stage(kc + 1, cur ^ 1); CP_COMMIT(); CP_WAIT1(); }
        else         { CP_WAIT0(); }
        __syncthreads();

        uint32_t ab = base + (uint32_t)(cur*8704)*2;
        uint32_t bb = base + (uint32_t)((2 + cur)*8704)*2;

        uint32_t a[4][4];
        #pragma unroll
        for (int ks = 0; ks < 4; ks++)
            ldsm_x4t(a[ks], ab + (uint32_t)((ks*16 + arow)*136 + acol)*2);
        #pragma unroll
        for (int ks = 0; ks < 4; ks++) {
            #pragma unroll
            for (int u = 0; u < 8; u++) {
                uint32_t bf[4];
                ldsm_x4t(bf, bb + (uint32_t)((ks*16 + brow)*136 + u*16 + bcol)*2);
                mma_bf16(o[2*u],   a[ks], bf[0], bf[1]);
                mma_bf16(o[2*u+1], a[ks], bf[2], bf[3]);
            }
        }
        __syncthreads();
    }

    float bb0 = b3[q0 + g];
    float bb1 = b3[q0 + g + 8];
    #pragma unroll
    for (int ct = 0; ct < 16; ct++) {
        size_t a0 = ((size_t)b*C_ + q0 + g)*HW_ + pt*128 + ct*8 + 2*t;
        size_t a1 = ((size_t)b*C_ + q0 + g + 8)*HW_ + pt*128 + ct*8 + 2*t;
        float2 x0 = *(const float2*)&x[a0];
        float2 x1 = *(const float2*)&x[a1];
        *(float2*)&out[a0] = make_float2(o[ct][0] + bb0 + x0.x, o[ct][1] + bb0 + x0.y);
        *(float2*)&out[a1] = make_float2(o[ct][2] + bb1 + x1.x, o[ct][3] + bb1 + x1.y);
    }
}

// ---------------------------------------------------------------------------
extern "C" void kernel_launch(void* const* d_in, const int* in_sizes, int n_in,
                              void* d_out, int out_size)
{
    const float* x      = (const float*)d_in[0];
    const float* q_cond = (const float*)d_in[1];
    const float* ka     = (const float*)d_in[2];
    const float* kb     = (const float*)d_in[3];
    const float* gs     = (const float*)d_in[4];
    const float* gb     = (const float*)d_in[5];
    const float* W0 = (const float*)d_in[6];  const float* b0 = (const float*)d_in[7];
    const float* W1 = (const float*)d_in[8];  const float* b1 = (const float*)d_in[9];
    const float* W2 = (const float*)d_in[10]; const float* b2 = (const float*)d_in[11];
    const float* W3 = (const float*)d_in[12]; const float* b3 = (const float*)d_in[13];
    float* out = (float*)d_out;

    __nv_bfloat16 *h16, *q16, *k16, *v16, *hh16;
    cudaGetSymbolAddress((void**)&h16,  g_h16);
    cudaGetSymbolAddress((void**)&q16,  g_q16);
    cudaGetSymbolAddress((void**)&k16,  g_k16);
    cudaGetSymbolAddress((void**)&v16,  g_v16);
    cudaGetSymbolAddress((void**)&hh16, g_hh16);

    cudaFuncSetAttribute(attn_bf16_kernel,
                         cudaFuncAttributeMaxDynamicSharedMemorySize, ATTN_SMEM);
    const int out_smem = 4 * 8704 * 2;  // 69632 B
    cudaFuncSetAttribute(out_bf16_kernel,
                         cudaFuncAttributeMaxDynamicSharedMemorySize, out_smem);

    dim3 cg(256, 7);
    cvt_kernel<<<cg, 256>>>(W0, W1, W2, W3, q_cond, ka, kb);

    gn_kernel<<<512, 256>>>(x, gs, gb, h16);

    dim3 pg(8, 4, 48);
    proj_bf16_kernel<<<pg, 256>>>(h16, b0, b1, b2, q16, k16, v16);

    dim3 ag(8, 96);
    attn_bf16_kernel<<<ag, 256, ATTN_SMEM>>>(q16, k16, v16, hh16);

    dim3 og(8, 16);
    out_bf16_kernel<<<og, 256, out_smem>>>(hh16, b3, x, out);
}